// round 4
// baseline (speedup 1.0000x reference)
#include <cuda_runtime.h>
#include <math.h>

#define NODE   30000
#define NPAD   30080
#define HID    128
#define NE     600000
#define NBATCH 4096
#define AROWS  8192
#define GAMMA_F 3.0f
#define LAMB_F  30.0f
#define TAU_F   10.0f

// ---------------- device globals (scratch; no allocs allowed) ----------------
__device__ float  g_feat[(size_t)NPAD * HID];   // 15.4 MB, L2-resident
__device__ float  g_deg[NODE];
__device__ float  g_inv[NODE];
__device__ float  g_sqn[NPAD];
__device__ float  g_pos[NBATCH];
__device__ float  g_X[(size_t)AROWS * NPAD];    // 986 MB workspace
__device__ double g_acc;
__device__ int    g_tp64, g_adj64;

__device__ __forceinline__ int readIdx(const void* p, long long i, int is64) {
    if (is64) return (int)((const long long*)p)[i];
    return ((const int*)p)[i];
}

// ---------------- dtype detection (int32 vs int64 index arrays) --------------
__global__ void k_detect(const void* tp, const void* adj) {
    if (threadIdx.x == 0 && blockIdx.x == 0) {
        const int* a = (const int*)tp;
        int all0 = 1;
        for (int k = 0; k < 16; k++) if (a[2 * k + 1] != 0) all0 = 0;
        g_tp64 = all0;
        const int* b = (const int*)adj;
        all0 = 1;
        for (int k = 0; k < 16; k++) if (b[2 * k + 1] != 0) all0 = 0;
        g_adj64 = all0;
    }
}

// ---------------- zero feat/deg/acc ----------------
__global__ void k_zero() {
    size_t i = (size_t)blockIdx.x * blockDim.x + threadIdx.x;
    size_t stride = (size_t)gridDim.x * blockDim.x;
    float4 z = make_float4(0.f, 0.f, 0.f, 0.f);
    float4* f4 = (float4*)g_feat;
    size_t n4 = (size_t)NPAD * HID / 4;
    for (size_t j = i; j < n4; j += stride) f4[j] = z;
    for (size_t j = i; j < NODE; j += stride) g_deg[j] = 0.f;
    if (i == 0) g_acc = 0.0;
}

// ---------------- degree ----------------
__global__ void k_deg(const void* adj) {
    int e = blockIdx.x * blockDim.x + threadIdx.x;
    int is64 = g_adj64;
    if (e < NE) atomicAdd(&g_deg[readIdx(adj, e, is64)], 1.0f);
}

__global__ void k_inv() {
    int i = blockIdx.x * blockDim.x + threadIdx.x;
    if (i < NODE) {
        float d = g_deg[i];
        g_inv[i] = (d > 0.f) ? (1.0f / d) : 1.0f;
    }
}

// ---------------- feat scatter: warp per edge, lane per float4 ----------------
__global__ void k_scatter(const void* adj, const float* emb) {
    long long idx = (long long)blockIdx.x * blockDim.x + threadIdx.x;
    if (idx >= (long long)NE * 32) return;
    int e = (int)(idx >> 5);
    int lane = (int)(idx & 31);
    int is64 = g_adj64;
    int r = readIdx(adj, e, is64);
    int c = readIdx(adj, (long long)NE + e, is64);
    float w = g_inv[r];
    float4 v = ((const float4*)emb)[(size_t)c * 32 + lane];
    float4 o = make_float4(v.x * w, v.y * w, v.z * w, v.w * w);
    atomicAdd(((float4*)g_feat) + (size_t)r * 32 + lane, o);  // red.global.v4.f32 (sm_90+)
}

// ---------------- squared norms, warp per node ----------------
__global__ void k_sqn() {
    int t = blockIdx.x * blockDim.x + threadIdx.x;
    int warp = t >> 5, lane = t & 31;
    if (warp >= NPAD) return;
    float4 v = ((const float4*)g_feat)[(size_t)warp * 32 + lane];
    float s = v.x * v.x + v.y * v.y + v.z * v.z + v.w * v.w;
    for (int o = 16; o; o >>= 1) s += __shfl_xor_sync(0xffffffffu, s, o);
    if (lane == 0) g_sqn[warp] = s;
}

// ---------------- pos_dis, warp per pair ----------------
__global__ void k_pos(const void* tp) {
    int t = blockIdx.x * blockDim.x + threadIdx.x;
    int warp = t >> 5, lane = t & 31;
    if (warp >= NBATCH) return;
    int is64 = g_tp64;
    int l = readIdx(tp, 2LL * warp, is64);
    int r = readIdx(tp, 2LL * warp + 1, is64);
    float4 a = ((const float4*)g_feat)[(size_t)l * 32 + lane];
    float4 b = ((const float4*)g_feat)[(size_t)r * 32 + lane];
    float dx = a.x - b.x, dy = a.y - b.y, dz = a.z - b.z, dw = a.w - b.w;
    float s = dx * dx + dy * dy + dz * dz + dw * dw;
    for (int o = 16; o; o >>= 1) s += __shfl_xor_sync(0xffffffffu, s, o);
    if (lane == 0) g_pos[warp] = s;
}

// ---------------- fused GEMM + loss epilogue ----------------
// C tile: BM=64 A-rows x BN=128 j-cols, 128 threads, thread tile 8x8, BK=32.
// Tiles stored k-major transposed in smem so inner loop is 4 LDS.128 / 64 FFMA.
__global__ __launch_bounds__(128) void k_gemm(const void* tp) {
    __shared__ float sA[32][68];    // [k][m], pad 4 keeps float4 align, kills STS conflicts mostly
    __shared__ float sF[32][132];   // [k][n]
    __shared__ float s_sqa[64], s_pos[64];
    __shared__ int   s_aidx[64], s_l[64], s_r[64];
    __shared__ float s_sqnj[128];

    const int tid = threadIdx.x;
    const int bn = blockIdx.x;      // 0..234
    const int bm = blockIdx.y;      // 0..127
    const int is64 = g_tp64;

    if (tid < 64) {
        int g = bm * 64 + tid;
        int pair = g >> 1, side = g & 1;
        int a = readIdx(tp, 2LL * pair + side, is64);
        s_aidx[tid] = a;
        s_sqa[tid] = g_sqn[a];
        s_pos[tid] = g_pos[pair];
        s_l[tid] = readIdx(tp, 2LL * pair, is64);
        s_r[tid] = readIdx(tp, 2LL * pair + 1, is64);
    }
    s_sqnj[tid] = g_sqn[bn * 128 + tid];   // tid < 128 always; j < NPAD
    __syncthreads();

    float acc[8][8];
#pragma unroll
    for (int i = 0; i < 8; i++)
#pragma unroll
        for (int j = 0; j < 8; j++) acc[i][j] = 0.f;

    const int tn = tid & 15;   // 16 n-groups of 8
    const int tm = tid >> 4;   // 8 m-groups of 8

    for (int kc = 0; kc < 4; kc++) {
        // A tile: 64 rows x 32 k -> 512 float4, 4/thread (gathered via s_aidx)
#pragma unroll
        for (int i = 0; i < 4; i++) {
            int idx = tid + i * 128;           // 0..511
            int m = idx >> 3, k4 = idx & 7;
            const float4 v = *(const float4*)&g_feat[(size_t)s_aidx[m] * HID + kc * 32 + k4 * 4];
            sA[k4 * 4 + 0][m] = v.x;
            sA[k4 * 4 + 1][m] = v.y;
            sA[k4 * 4 + 2][m] = v.z;
            sA[k4 * 4 + 3][m] = v.w;
        }
        // F tile: 128 rows x 32 k -> 1024 float4, 8/thread
#pragma unroll
        for (int i = 0; i < 8; i++) {
            int idx = tid + i * 128;           // 0..1023
            int n = idx >> 3, k4 = idx & 7;
            const float4 v = *(const float4*)&g_feat[(size_t)(bn * 128 + n) * HID + kc * 32 + k4 * 4];
            sF[k4 * 4 + 0][n] = v.x;
            sF[k4 * 4 + 1][n] = v.y;
            sF[k4 * 4 + 2][n] = v.z;
            sF[k4 * 4 + 3][n] = v.w;
        }
        __syncthreads();
#pragma unroll 4
        for (int k = 0; k < 32; k++) {
            float av[8], fv[8];
            *(float4*)&av[0] = *(const float4*)&sA[k][tm * 8];
            *(float4*)&av[4] = *(const float4*)&sA[k][tm * 8 + 4];
            *(float4*)&fv[0] = *(const float4*)&sF[k][tn * 8];
            *(float4*)&fv[4] = *(const float4*)&sF[k][tn * 8 + 4];
#pragma unroll
            for (int i = 0; i < 8; i++)
#pragma unroll
                for (int j = 0; j < 8; j++) acc[i][j] += av[i] * fv[j];
        }
        __syncthreads();
    }

    // epilogue: x = (pos - sqa - sqn_j + 2*dot + GAMMA) * mask
#pragma unroll
    for (int i = 0; i < 8; i++) {
        int m = tm * 8 + i;
        float pos = s_pos[m], sqa = s_sqa[m];
        int l = s_l[m], r = s_r[m];
        size_t base = (size_t)(bm * 64 + m) * NPAD + bn * 128 + tn * 8;
        float o[8];
#pragma unroll
        for (int jj = 0; jj < 8; jj++) {
            int j = bn * 128 + tn * 8 + jj;
            float x = pos - sqa - s_sqnj[tn * 8 + jj] + 2.0f * acc[i][jj] + GAMMA_F;
            float mask = 1.0f - (float)(j == l) - (float)(j == r);
            o[jj] = x * mask;
        }
        *(float4*)&g_X[base] = *(float4*)&o[0];
        *(float4*)&g_X[base + 4] = *(float4*)&o[4];
    }
}

// ---------------- per-row stats + logsumexp ----------------
__device__ __forceinline__ float warpSum(float v) {
    for (int o = 16; o; o >>= 1) v += __shfl_xor_sync(0xffffffffu, v, o);
    return v;
}
__device__ __forceinline__ float warpMaxR(float v) {
    for (int o = 16; o; o >>= 1) v = fmaxf(v, __shfl_xor_sync(0xffffffffu, v, o));
    return v;
}
__device__ float blockSum(float v) {
    __shared__ float scr[8];
    __shared__ float bc;
    v = warpSum(v);
    if ((threadIdx.x & 31) == 0) scr[threadIdx.x >> 5] = v;
    __syncthreads();
    if (threadIdx.x < 32) {
        float t = (threadIdx.x < 8) ? scr[threadIdx.x] : 0.f;
        t = warpSum(t);
        if (threadIdx.x == 0) bc = t;
    }
    __syncthreads();
    float r = bc;
    __syncthreads();
    return r;
}
__device__ float blockMax(float v) {
    __shared__ float scr[8];
    __shared__ float bc;
    v = warpMaxR(v);
    if ((threadIdx.x & 31) == 0) scr[threadIdx.x >> 5] = v;
    __syncthreads();
    if (threadIdx.x < 32) {
        float t = (threadIdx.x < 8) ? scr[threadIdx.x] : -3.4e38f;
        t = warpMaxR(t);
        if (threadIdx.x == 0) bc = t;
    }
    __syncthreads();
    float r = bc;
    __syncthreads();
    return r;
}

__global__ __launch_bounds__(256) void k_stats() {
    extern __shared__ float srow[];            // 30000 floats = 120000 B
    const int tid = threadIdx.x;
    const float4* x4 = (const float4*)(g_X + (size_t)blockIdx.x * NPAD);
    float4* s4 = (float4*)srow;

    float sum = 0.f, mx = -3.4e38f;
    for (int i = tid; i < 7500; i += 256) {    // 7500*4 = 30000 real columns
        float4 v = x4[i];
        s4[i] = v;
        sum += (v.x + v.y) + (v.z + v.w);
        mx = fmaxf(mx, fmaxf(fmaxf(v.x, v.y), fmaxf(v.z, v.w)));
    }
    __syncthreads();
    float tot  = blockSum(sum);
    float xmax = blockMax(mx);
    float mean = tot / 30000.0f;

    float vs = 0.f;
    for (int i = tid; i < 7500; i += 256) {
        float4 v = s4[i];
        float d0 = v.x - mean, d1 = v.y - mean, d2 = v.z - mean, d3 = v.w - mean;
        vs += d0 * d0 + d1 * d1 + d2 * d2 + d3 * d3;
    }
    float var = blockSum(vs) / 30000.0f;
    float a = LAMB_F / sqrtf(var);

    float se = 0.f;
    for (int i = tid; i < 7500; i += 256) {
        float4 v = s4[i];
        se += __expf(a * (v.x - xmax)) + __expf(a * (v.y - xmax)) +
              __expf(a * (v.z - xmax)) + __expf(a * (v.w - xmax));
    }
    float setot = blockSum(se);
    if (tid == 0) {
        float lse = a * (xmax - mean) + TAU_F + logf(setot);
        atomicAdd(&g_acc, (double)lse);
    }
}

__global__ void k_final(float* out) {
    if (threadIdx.x == 0 && blockIdx.x == 0)
        out[0] = (float)(g_acc / (double)NBATCH);
}

// ---------------- launch ----------------
extern "C" void kernel_launch(void* const* d_in, const int* in_sizes, int n_in,
                              void* d_out, int out_size) {
    const void* tp = nullptr;
    const void* adj = nullptr;
    const float* emb = nullptr;
    for (int i = 0; i < n_in; i++) {
        if (in_sizes[i] == NBATCH * 2)        tp  = d_in[i];
        else if (in_sizes[i] == 2 * NE)       adj = d_in[i];
        else if (in_sizes[i] == NODE * HID)   emb = (const float*)d_in[i];
    }
    float* out = (float*)d_out;

    k_detect<<<1, 32>>>(tp, adj);
    k_zero<<<2048, 256>>>();
    k_deg<<<(NE + 255) / 256, 256>>>(adj);
    k_inv<<<(NODE + 255) / 256, 256>>>();
    k_scatter<<<(int)(((long long)NE * 32 + 255) / 256), 256>>>(adj, emb);
    k_sqn<<<(NPAD * 32 + 255) / 256, 256>>>();
    k_pos<<<(NBATCH * 32 + 255) / 256, 256>>>(tp);

    dim3 gg(NPAD / 128, AROWS / 64);   // (235, 128)
    k_gemm<<<gg, 128>>>(tp);

    cudaFuncSetAttribute(k_stats, cudaFuncAttributeMaxDynamicSharedMemorySize, 120000);
    k_stats<<<AROWS, 256, 120000>>>();

    k_final<<<1, 1>>>(out);
}

// round 6
// speedup vs baseline: 2.5516x; 2.5516x over previous
#include <cuda_runtime.h>
#include <cuda_fp16.h>
#include <math.h>
#include <stdint.h>

#define NODE   30000
#define NPAD   30080
#define HID    128
#define NE     600000
#define NBATCH 4096
#define AROWS  8192
#define GAMMA_F 3.0f
#define LAMB_F  30.0f
#define TAU_F   10.0f

// ---------------- device globals (scratch; no allocs allowed) ----------------
__device__ float  g_feat[(size_t)NPAD * HID];   // 15.4 MB, mostly L2-resident
__device__ float  g_deg[NODE];
__device__ float  g_inv[NODE];
__device__ float  g_sqn[NPAD];
__device__ float  g_pos[NBATCH];
__device__ __half g_Y[(size_t)AROWS * NPAD];    // 493 MB: y = x*mask - c_m in fp16
__device__ double g_acc;
__device__ int    g_tp64, g_adj64;

__device__ __forceinline__ int readIdx(const void* p, long long i, int is64) {
    if (is64) return (int)((const long long*)p)[i];
    return ((const int*)p)[i];
}

__device__ __forceinline__ uint32_t smem_u32(const void* p) {
    uint32_t a;
    asm("{ .reg .u64 t; cvta.to.shared.u64 t, %1; cvt.u32.u64 %0, t; }" : "=r"(a) : "l"(p));
    return a;
}
__device__ __forceinline__ void cp_async16(uint32_t s, const void* g) {
    asm volatile("cp.async.cg.shared.global [%0], [%1], 16;" :: "r"(s), "l"(g));
}
__device__ __forceinline__ void cp_commit() {
    asm volatile("cp.async.commit_group;" ::: "memory");
}
// mma.sync m16n8k8 tf32 (HMMA fallback path; no sm_103a gating)
__device__ __forceinline__ void mma_tf32(float* d, const uint32_t* a, const uint32_t* b) {
    asm volatile(
        "mma.sync.aligned.m16n8k8.row.col.f32.tf32.tf32.f32 "
        "{%0,%1,%2,%3}, {%4,%5,%6,%7}, {%8,%9}, {%0,%1,%2,%3};"
        : "+f"(d[0]), "+f"(d[1]), "+f"(d[2]), "+f"(d[3])
        : "r"(a[0]), "r"(a[1]), "r"(a[2]), "r"(a[3]), "r"(b[0]), "r"(b[1]));
}

// ---------------- dtype detection (int32 vs int64 index arrays) --------------
__global__ void k_detect(const void* tp, const void* adj) {
    if (threadIdx.x == 0 && blockIdx.x == 0) {
        const int* a = (const int*)tp;
        int all0 = 1;
        for (int k = 0; k < 16; k++) if (a[2 * k + 1] != 0) all0 = 0;
        g_tp64 = all0;
        const int* b = (const int*)adj;
        all0 = 1;
        for (int k = 0; k < 16; k++) if (b[2 * k + 1] != 0) all0 = 0;
        g_adj64 = all0;
    }
}

__global__ void k_zero() {
    size_t i = (size_t)blockIdx.x * blockDim.x + threadIdx.x;
    size_t stride = (size_t)gridDim.x * blockDim.x;
    float4 z = make_float4(0.f, 0.f, 0.f, 0.f);
    float4* f4 = (float4*)g_feat;
    size_t n4 = (size_t)NPAD * HID / 4;
    for (size_t j = i; j < n4; j += stride) f4[j] = z;
    for (size_t j = i; j < NODE; j += stride) g_deg[j] = 0.f;
    if (i == 0) g_acc = 0.0;
}

__global__ void k_deg(const void* adj) {
    int e = blockIdx.x * blockDim.x + threadIdx.x;
    int is64 = g_adj64;
    if (e < NE) atomicAdd(&g_deg[readIdx(adj, e, is64)], 1.0f);
}

__global__ void k_inv() {
    int i = blockIdx.x * blockDim.x + threadIdx.x;
    if (i < NODE) {
        float d = g_deg[i];
        g_inv[i] = (d > 0.f) ? (1.0f / d) : 1.0f;
    }
}

__global__ void k_scatter(const void* adj, const float* emb) {
    long long idx = (long long)blockIdx.x * blockDim.x + threadIdx.x;
    if (idx >= (long long)NE * 32) return;
    int e = (int)(idx >> 5);
    int lane = (int)(idx & 31);
    int is64 = g_adj64;
    int r = readIdx(adj, e, is64);
    int c = readIdx(adj, (long long)NE + e, is64);
    float w = g_inv[r];
    float4 v = ((const float4*)emb)[(size_t)c * 32 + lane];
    float4 o = make_float4(v.x * w, v.y * w, v.z * w, v.w * w);
    atomicAdd(((float4*)g_feat) + (size_t)r * 32 + lane, o);
}

__global__ void k_sqn() {
    int t = blockIdx.x * blockDim.x + threadIdx.x;
    int warp = t >> 5, lane = t & 31;
    if (warp >= NPAD) return;
    float4 v = ((const float4*)g_feat)[(size_t)warp * 32 + lane];
    float s = v.x * v.x + v.y * v.y + v.z * v.z + v.w * v.w;
    for (int o = 16; o; o >>= 1) s += __shfl_xor_sync(0xffffffffu, s, o);
    if (lane == 0) g_sqn[warp] = s;
}

__global__ void k_pos(const void* tp) {
    int t = blockIdx.x * blockDim.x + threadIdx.x;
    int warp = t >> 5, lane = t & 31;
    if (warp >= NBATCH) return;
    int is64 = g_tp64;
    int l = readIdx(tp, 2LL * warp, is64);
    int r = readIdx(tp, 2LL * warp + 1, is64);
    float4 a = ((const float4*)g_feat)[(size_t)l * 32 + lane];
    float4 b = ((const float4*)g_feat)[(size_t)r * 32 + lane];
    float dx = a.x - b.x, dy = a.y - b.y, dz = a.z - b.z, dw = a.w - b.w;
    float s = dx * dx + dy * dy + dz * dz + dw * dw;
    for (int o = 16; o; o >>= 1) s += __shfl_xor_sync(0xffffffffu, s, o);
    if (lane == 0) g_pos[warp] = s;
}

// ---------------- tf32 mma.sync GEMM + fused loss epilogue ----------------
// CTA: 256 thr (8 warps, 2m x 4n), BM=128 (A rows gathered, persistent in smem),
// BN=128 per chunk, B double-buffered via cp.async. Warp tile 64x32 =
// 4x4 m16n8k8 tiles, 16 k-steps (K=128). Epilogue: y = mask*x - c_m -> fp16.
#define SROW 132   // padded float stride (conflict-free quad access)

__global__ __launch_bounds__(256, 1) void k_mma(const void* tp) {
    extern __shared__ uint32_t dsm[];
    uint32_t* sA  = dsm;                 // 128 x SROW
    uint32_t* sB0 = sA + 128 * SROW;
    uint32_t* sB1 = sB0 + 128 * SROW;
    __shared__ int   s_aidx[128], s_l[128], s_r[128];
    __shared__ float s_cm[128];
    __shared__ float s_sqnj[2][128];

    const int tid = threadIdx.x;
    const int lane = tid & 31;
    const int warp = tid >> 5;
    const int wm = warp >> 2;            // 0..1 -> m offset 0/64
    const int wn = warp & 3;             // 0..3 -> n offset 0/32/64/96
    const int qrow = lane >> 2;          // 0..7
    const int qcol = lane & 3;           // 0..3
    const int bm = blockIdx.y;
    const int sx = blockIdx.x;
    const int is64 = g_tp64;

    if (tid < 128) {
        int g = bm * 128 + tid;
        int pair = g >> 1, side = g & 1;
        int a = readIdx(tp, 2LL * pair + side, is64);
        s_aidx[tid] = a;
        s_l[tid] = readIdx(tp, 2LL * pair, is64);
        s_r[tid] = readIdx(tp, 2LL * pair + 1, is64);
        s_cm[tid] = g_pos[pair] - g_sqn[a] + GAMMA_F;
    }
    __syncthreads();

    const uint32_t sAaddr  = smem_u32(sA);
    const uint32_t sBaddr[2] = { smem_u32(sB0), smem_u32(sB1) };

    // A tile: 128 rows x 32 float4 gathered via cp.async (group with chunk 0)
#pragma unroll
    for (int q = 0; q < 16; q++) {
        int idx = tid + q * 256;         // 0..4095
        int r = idx >> 5, k4 = idx & 31;
        cp_async16(sAaddr + (r * SROW + k4 * 4) * 4,
                   &g_feat[(size_t)s_aidx[r] * HID + k4 * 4]);
    }

    const int c0 = (235 * sx) / 7;
    const int c1 = (235 * (sx + 1)) / 7;
    const int nch = c1 - c0;

    // prefetch B chunk 0 (same commit group as A)
    {
        int nb = c0 * 128;
#pragma unroll
        for (int q = 0; q < 16; q++) {
            int idx = tid + q * 256;
            int r = idx >> 5, k4 = idx & 31;
            cp_async16(sBaddr[0] + (r * SROW + k4 * 4) * 4,
                       &g_feat[(size_t)(nb + r) * HID + k4 * 4]);
        }
        if (tid < 128) s_sqnj[0][tid] = g_sqn[nb + tid];
        cp_commit();
    }

    for (int i = 0; i < nch; i++) {
        const int b = i & 1;
        if (i + 1 < nch) {
            int nb = (c0 + i + 1) * 128;
            uint32_t dst = sBaddr[b ^ 1];
#pragma unroll
            for (int q = 0; q < 16; q++) {
                int idx = tid + q * 256;
                int r = idx >> 5, k4 = idx & 31;
                cp_async16(dst + (r * SROW + k4 * 4) * 4,
                           &g_feat[(size_t)(nb + r) * HID + k4 * 4]);
            }
            if (tid < 128) s_sqnj[b ^ 1][tid] = g_sqn[nb + tid];
            cp_commit();
            asm volatile("cp.async.wait_group 1;" ::: "memory");
        } else {
            asm volatile("cp.async.wait_group 0;" ::: "memory");
        }
        __syncthreads();

        // ---- compute 128x128 chunk ----
        float acc[4][4][4];
#pragma unroll
        for (int mi = 0; mi < 4; mi++)
#pragma unroll
            for (int ni = 0; ni < 4; ni++)
#pragma unroll
                for (int c = 0; c < 4; c++) acc[mi][ni][c] = 0.f;

        const uint32_t* sB = b ? sB1 : sB0;
        const uint32_t* pAb = sA + (wm * 64 + qrow) * SROW + qcol;
        const uint32_t* pBb = sB + (wn * 32 + qrow) * SROW + qcol;

#pragma unroll 4
        for (int ks = 0; ks < 16; ks++) {
            uint32_t af[4][4], bf[4][2];
#pragma unroll
            for (int mi = 0; mi < 4; mi++) {
                const uint32_t* p = pAb + mi * 16 * SROW + ks * 8;
                af[mi][0] = p[0];
                af[mi][1] = p[8 * SROW];
                af[mi][2] = p[4];
                af[mi][3] = p[8 * SROW + 4];
            }
#pragma unroll
            for (int ni = 0; ni < 4; ni++) {
                const uint32_t* p = pBb + ni * 8 * SROW + ks * 8;
                bf[ni][0] = p[0];
                bf[ni][1] = p[4];
            }
#pragma unroll
            for (int mi = 0; mi < 4; mi++)
#pragma unroll
                for (int ni = 0; ni < 4; ni++)
                    mma_tf32(acc[mi][ni], af[mi], bf[ni]);
        }

        // ---- epilogue: y = mask*(cm + 2*dot - sqn_j) - cm, fp16 store ----
        const int jchunk = (c0 + i) * 128;
#pragma unroll
        for (int mi = 0; mi < 4; mi++) {
            int r0 = wm * 64 + mi * 16 + qrow;
            int r1 = r0 + 8;
            float cm0 = s_cm[r0], cm1 = s_cm[r1];
            int l0 = s_l[r0], rr0 = s_r[r0];
            int l1 = s_l[r1], rr1 = s_r[r1];
            size_t g0 = (size_t)(bm * 128 + r0) * NPAD + jchunk;
            size_t g1 = (size_t)(bm * 128 + r1) * NPAD + jchunk;
#pragma unroll
            for (int ni = 0; ni < 4; ni++) {
                int c = wn * 32 + ni * 8 + qcol * 2;
                int j0 = jchunk + c, j1 = j0 + 1;
                float sq0 = s_sqnj[b][c], sq1 = s_sqnj[b][c + 1];
                float m00 = 1.0f - (float)(j0 == l0) - (float)(j0 == rr0);
                float m01 = 1.0f - (float)(j1 == l0) - (float)(j1 == rr0);
                float m10 = 1.0f - (float)(j0 == l1) - (float)(j0 == rr1);
                float m11 = 1.0f - (float)(j1 == l1) - (float)(j1 == rr1);
                float y00 = fmaf(m00, cm0 + fmaf(2.f, acc[mi][ni][0], -sq0), -cm0);
                float y01 = fmaf(m01, cm0 + fmaf(2.f, acc[mi][ni][1], -sq1), -cm0);
                float y10 = fmaf(m10, cm1 + fmaf(2.f, acc[mi][ni][2], -sq0), -cm1);
                float y11 = fmaf(m11, cm1 + fmaf(2.f, acc[mi][ni][3], -sq1), -cm1);
                __half2 h0 = __floats2half2_rn(y00, y01);
                __half2 h1 = __floats2half2_rn(y10, y11);
                *(__half2*)(g_Y + g0 + c) = h0;
                *(__half2*)(g_Y + g1 + c) = h1;
            }
        }
        __syncthreads();   // protect sB[b] / s_sqnj[b] before reuse
    }
}

// ---------------- per-row stats + logsumexp (fp16 y input) ----------------
__device__ __forceinline__ float warpSum(float v) {
    for (int o = 16; o; o >>= 1) v += __shfl_xor_sync(0xffffffffu, v, o);
    return v;
}
__device__ __forceinline__ float warpMaxR(float v) {
    for (int o = 16; o; o >>= 1) v = fmaxf(v, __shfl_xor_sync(0xffffffffu, v, o));
    return v;
}
__device__ float blockSum(float v) {
    __shared__ float scr[8];
    __shared__ float bc;
    v = warpSum(v);
    if ((threadIdx.x & 31) == 0) scr[threadIdx.x >> 5] = v;
    __syncthreads();
    if (threadIdx.x < 32) {
        float t = (threadIdx.x < 8) ? scr[threadIdx.x] : 0.f;
        t = warpSum(t);
        if (threadIdx.x == 0) bc = t;
    }
    __syncthreads();
    float r = bc;
    __syncthreads();
    return r;
}
__device__ float blockMax(float v) {
    __shared__ float scr[8];
    __shared__ float bc;
    v = warpMaxR(v);
    if ((threadIdx.x & 31) == 0) scr[threadIdx.x >> 5] = v;
    __syncthreads();
    if (threadIdx.x < 32) {
        float t = (threadIdx.x < 8) ? scr[threadIdx.x] : -3.4e38f;
        t = warpMaxR(t);
        if (threadIdx.x == 0) bc = t;
    }
    __syncthreads();
    float r = bc;
    __syncthreads();
    return r;
}

__device__ __forceinline__ void unpack8(uint4 v, float* f) {
    float2 a = __half22float2(*(__half2*)&v.x);
    float2 b = __half22float2(*(__half2*)&v.y);
    float2 c = __half22float2(*(__half2*)&v.z);
    float2 d = __half22float2(*(__half2*)&v.w);
    f[0] = a.x; f[1] = a.y; f[2] = b.x; f[3] = b.y;
    f[4] = c.x; f[5] = c.y; f[6] = d.x; f[7] = d.y;
}

__global__ __launch_bounds__(256) void k_stats() {
    extern __shared__ uint4 srow4[];           // 3750 uint4 = 30000 halves
    const int tid = threadIdx.x;
    const uint4* x4 = (const uint4*)(g_Y + (size_t)blockIdx.x * NPAD);

    float sum = 0.f, mx = -3.4e38f;
    for (int i = tid; i < 3750; i += 256) {
        uint4 v = x4[i];
        srow4[i] = v;
        float f[8];
        unpack8(v, f);
#pragma unroll
        for (int c = 0; c < 8; c++) { sum += f[c]; mx = fmaxf(mx, f[c]); }
    }
    __syncthreads();
    float tot  = blockSum(sum);
    float ymax = blockMax(mx);
    float mean = tot / 30000.0f;

    float vs = 0.f;
    for (int i = tid; i < 3750; i += 256) {
        float f[8];
        unpack8(srow4[i], f);
#pragma unroll
        for (int c = 0; c < 8; c++) { float d = f[c] - mean; vs += d * d; }
    }
    float var = blockSum(vs) / 30000.0f;
    float a = LAMB_F / sqrtf(var);

    float se = 0.f;
    for (int i = tid; i < 3750; i += 256) {
        float f[8];
        unpack8(srow4[i], f);
#pragma unroll
        for (int c = 0; c < 8; c++) se += __expf(a * (f[c] - ymax));
    }
    float setot = blockSum(se);
    if (tid == 0) {
        float lse = a * (ymax - mean) + TAU_F + logf(setot);
        atomicAdd(&g_acc, (double)lse);
    }
}

__global__ void k_final(float* out) {
    if (threadIdx.x == 0 && blockIdx.x == 0)
        out[0] = (float)(g_acc / (double)NBATCH);
}

// ---------------- launch ----------------
extern "C" void kernel_launch(void* const* d_in, const int* in_sizes, int n_in,
                              void* d_out, int out_size) {
    const void* tp = nullptr;
    const void* adj = nullptr;
    const float* emb = nullptr;
    for (int i = 0; i < n_in; i++) {
        if (in_sizes[i] == NBATCH * 2)        tp  = d_in[i];
        else if (in_sizes[i] == 2 * NE)       adj = d_in[i];
        else if (in_sizes[i] == NODE * HID)   emb = (const float*)d_in[i];
    }
    float* out = (float*)d_out;

    k_detect<<<1, 32>>>(tp, adj);
    k_zero<<<2048, 256>>>();
    k_deg<<<(NE + 255) / 256, 256>>>(adj);
    k_inv<<<(NODE + 255) / 256, 256>>>();
    k_scatter<<<(int)(((long long)NE * 32 + 255) / 256), 256>>>(adj, emb);
    k_sqn<<<(NPAD * 32 + 255) / 256, 256>>>();
    k_pos<<<(NBATCH * 32 + 255) / 256, 256>>>(tp);

    // dynamic smem: 3 tiles x 128 x 132 floats = 202752 B
    cudaFuncSetAttribute(k_mma, cudaFuncAttributeMaxDynamicSharedMemorySize, 202752);
    dim3 gg(7, 64);   // 7 n-splits x 64 m-tiles = 448 CTAs
    k_mma<<<gg, 256, 202752>>>(tp);

    cudaFuncSetAttribute(k_stats, cudaFuncAttributeMaxDynamicSharedMemorySize, 60032);
    k_stats<<<AROWS, 256, 60032>>>();

    k_final<<<1, 1>>>(out);
}

// round 7
// speedup vs baseline: 2.5777x; 1.0103x over previous
#include <cuda_runtime.h>
#include <cuda_fp16.h>
#include <math.h>
#include <stdint.h>

#define NODE   30000
#define NPAD   30080
#define HID    128
#define NE     600000
#define NBATCH 4096
#define AROWS  8192
#define NCHUNK 235          // NPAD/128
#define NBM    64           // AROWS/128
#define TOTW   (NBM * NCHUNK)
#define GRID_MMA 148
#define GAMMA_F 3.0f
#define LAMB_F  30.0f
#define TAU_F   10.0f

// ---------------- device globals ----------------
__device__ float  g_feat[(size_t)NPAD * HID];    // raw aggregated f' (unnormalized)
__device__ float  g_featP[(size_t)NPAD * HID];   // k-permuted copy for MMA fragments
__device__ float  g_deg[NODE];
__device__ float  g_sqn[NPAD];                   // normalized squared norms
__device__ float  g_winv[NPAD];                  // 1/deg (1 for pad)
__device__ float  g_pos[NBATCH];
__device__ __half g_Y[(size_t)AROWS * NPAD];     // y = mask*x - c_m, fp16
__device__ float  g_rsum[AROWS], g_rsum2[AROWS];
__device__ unsigned g_rmaxU[AROWS];
__device__ double g_acc;
__device__ int    g_tp64, g_adj64;

__device__ __forceinline__ int readIdx(const void* p, long long i, int is64) {
    if (is64) return (int)((const long long*)p)[i];
    return ((const int*)p)[i];
}
__device__ __forceinline__ uint32_t smem_u32(const void* p) {
    uint32_t a;
    asm("{ .reg .u64 t; cvta.to.shared.u64 t, %1; cvt.u32.u64 %0, t; }" : "=r"(a) : "l"(p));
    return a;
}
__device__ __forceinline__ void cp_async16(uint32_t s, const void* g) {
    asm volatile("cp.async.cg.shared.global [%0], [%1], 16;" :: "r"(s), "l"(g));
}
__device__ __forceinline__ void cp_commit() {
    asm volatile("cp.async.commit_group;" ::: "memory");
}
__device__ __forceinline__ void mma_tf32(float* d, const uint32_t* a, const uint32_t* b) {
    asm volatile(
        "mma.sync.aligned.m16n8k8.row.col.f32.tf32.tf32.f32 "
        "{%0,%1,%2,%3}, {%4,%5,%6,%7}, {%8,%9}, {%0,%1,%2,%3};"
        : "+f"(d[0]), "+f"(d[1]), "+f"(d[2]), "+f"(d[3])
        : "r"(a[0]), "r"(a[1]), "r"(a[2]), "r"(a[3]), "r"(b[0]), "r"(b[1]));
}
// monotone float<->uint encoding for atomicMax over signed floats
__device__ __forceinline__ unsigned encf(float f) {
    unsigned u = __float_as_uint(f);
    return (u & 0x80000000u) ? ~u : (u | 0x80000000u);
}
__device__ __forceinline__ float decf(unsigned e) {
    return (e & 0x80000000u) ? __uint_as_float(e & 0x7FFFFFFFu) : __uint_as_float(~e);
}

// ---------------- launch 0: zero + dtype detect ----------------
__global__ void k_zero(const void* tp, const void* adj) {
    size_t i = (size_t)blockIdx.x * blockDim.x + threadIdx.x;
    size_t stride = (size_t)gridDim.x * blockDim.x;
    float4 z = make_float4(0.f, 0.f, 0.f, 0.f);
    float4* f4 = (float4*)g_feat;
    size_t n4 = (size_t)NPAD * HID / 4;
    for (size_t j = i; j < n4; j += stride) f4[j] = z;
    for (size_t j = i; j < NODE; j += stride) g_deg[j] = 0.f;
    for (size_t j = i; j < AROWS; j += stride) {
        g_rsum[j] = 0.f; g_rsum2[j] = 0.f; g_rmaxU[j] = encf(-3.0e38f);
    }
    if (i == 0) {
        g_acc = 0.0;
        const int* a = (const int*)tp;
        int all0 = 1;
        for (int k = 0; k < 16; k++) if (a[2 * k + 1] != 0) all0 = 0;
        g_tp64 = all0;
        const int* b = (const int*)adj;
        all0 = 1;
        for (int k = 0; k < 16; k++) if (b[2 * k + 1] != 0) all0 = 0;
        g_adj64 = all0;
    }
}

// ---------------- launch 1: scatter raw emb + degree ----------------
__global__ void k_scatter(const void* adj, const float* emb) {
    long long idx = (long long)blockIdx.x * blockDim.x + threadIdx.x;
    if (idx >= (long long)NE * 32) return;
    int e = (int)(idx >> 5);
    int lane = (int)(idx & 31);
    int is64 = g_adj64;
    int r = readIdx(adj, e, is64);
    int c = readIdx(adj, (long long)NE + e, is64);
    if (lane == 0) atomicAdd(&g_deg[r], 1.0f);
    float4 v = ((const float4*)emb)[(size_t)c * 32 + lane];
    atomicAdd(((float4*)g_feat) + (size_t)r * 32 + lane, v);
}

__device__ __forceinline__ float warpSum(float v) {
    for (int o = 16; o; o >>= 1) v += __shfl_xor_sync(0xffffffffu, v, o);
    return v;
}

// ---------------- launch 2: sqn + winv + permute + pos ----------------
// blocks [0,3760): 8 rows each (warp/row): sqn, winv, featP permute
// blocks [3760,4272): 8 pairs each: pos
__global__ __launch_bounds__(256) void k_prep(const void* tp) {
    const int tid = threadIdx.x, lane = tid & 31, w = tid >> 5;
    const int blk = blockIdx.x;
    if (blk < NPAD / 8) {
        int row = blk * 8 + w;
        float4 v = ((const float4*)g_feat)[(size_t)row * 32 + lane];
        float s = v.x * v.x + v.y * v.y + v.z * v.z + v.w * v.w;
        float stot = warpSum(s);
        float wgt = 1.0f;
        if (row < NODE) {
            float d = g_deg[row];
            wgt = (d > 0.f) ? (1.0f / d) : 1.0f;
        }
        if (lane == 0) {
            g_sqn[row] = wgt * wgt * stot;
            g_winv[row] = wgt;
        }
        // permute: element k=4*lane+i -> pos (k>>4)*16 + i*4 + (lane&3)
        int kg = lane >> 2, ss = lane & 3;
        float* dst = &g_featP[(size_t)row * 128 + kg * 16 + ss];
        dst[0] = v.x; dst[4] = v.y; dst[8] = v.z; dst[12] = v.w;
    } else {
        int pr = (blk - NPAD / 8) * 8 + w;
        int is64 = g_tp64;
        int l = readIdx(tp, 2LL * pr, is64);
        int r = readIdx(tp, 2LL * pr + 1, is64);
        float dl = g_deg[l], dr = g_deg[r];
        float wl = (dl > 0.f) ? (1.0f / dl) : 1.0f;
        float wr = (dr > 0.f) ? (1.0f / dr) : 1.0f;
        float4 a = ((const float4*)g_feat)[(size_t)l * 32 + lane];
        float4 b = ((const float4*)g_feat)[(size_t)r * 32 + lane];
        float dx = wl * a.x - wr * b.x, dy = wl * a.y - wr * b.y;
        float dz = wl * a.z - wr * b.z, dw = wl * a.w - wr * b.w;
        float s = warpSum(dx * dx + dy * dy + dz * dz + dw * dw);
        if (lane == 0) g_pos[pr] = s;
    }
}

// ---------------- launch 3: persistent tf32 GEMM + fused epilogue+stats ----
// 148 persistent CTAs walk (bm, chunk) worklist. A (128 rows, gathered) held in
// smem per bm; B double-buffered via cp.async from featP (k-permuted + XOR-16B
// swizzle -> all fragment loads are conflict-free LDS.128 serving 2 ksteps).
// Epilogue: y = mask*(cm + 2*w_a*w_j*rd - sqn_j) - cm -> fp16 Y + per-row
// sum/sumsq/max accumulated in registers, flushed by atomics at bm switch.
__global__ __launch_bounds__(256, 1) void k_mma(const void* tp) {
    extern __shared__ float dsm[];
    float* sA = dsm;                       // 128 x 128 floats (64KB)
    float* sBb[2] = { dsm + 16384, dsm + 32768 };
    __shared__ float s_sqnj[2][128], s_wj[2][128];
    __shared__ float s_cm[128], s_wa2[128];
    __shared__ int   s_l[128], s_r[128];

    const int tid = threadIdx.x;
    const int lane = tid & 31, warp = tid >> 5;
    const int wm = warp >> 2, wn = warp & 3;        // 2m x 4n warps, 64x32 tiles
    const int qrow = lane >> 2, qcol = lane & 3;
    const int is64 = g_tp64;
    const uint32_t sAaddr = smem_u32(sA);
    const uint32_t sBaddr[2] = { smem_u32(sBb[0]), smem_u32(sBb[1]) };
    const uint32_t sqnjaddr = smem_u32(s_sqnj);
    const uint32_t wjaddr = smem_u32(s_wj);

    const long long t0 = ((long long)blockIdx.x * TOTW) / GRID_MMA;
    const long long t1 = ((long long)(blockIdx.x + 1) * TOTW) / GRID_MMA;
    if (t0 >= t1) return;

    int cur_bm = -1;
    float psum[8], psum2[8], pmax[8];
#pragma unroll
    for (int s = 0; s < 8; s++) { psum[s] = 0.f; psum2[s] = 0.f; pmax[s] = -3.0e38f; }

    // prefetch B for first work item
    {
        int ch = (int)(t0 % NCHUNK);
        int nb = ch * 128;
        uint32_t dst = sBaddr[0];
#pragma unroll
        for (int q = 0; q < 16; q++) {
            int idx = tid + q * 256;
            int row = idx >> 5, cc = idx & 31;
            cp_async16(dst + row * 512 + (((uint32_t)(cc ^ (row & 7))) << 4),
                       &g_featP[(size_t)(nb + row) * 128 + cc * 4]);
        }
        if (tid < 32) cp_async16(sqnjaddr + tid * 16, &g_sqn[nb + tid * 4]);
        else if (tid < 64) cp_async16(wjaddr + (tid - 32) * 16, &g_winv[nb + (tid - 32) * 4]);
        cp_commit();
    }

    for (long long t = t0; t < t1; t++) {
        const int b = (int)((t - t0) & 1);
        const int bm = (int)(t / NCHUNK);
        const int ch = (int)(t % NCHUNK);

        if (bm != cur_bm) {
            // flush stats of previous bm
            if (cur_bm >= 0) {
#pragma unroll
                for (int s = 0; s < 8; s++) {
                    float v = psum[s], v2 = psum2[s], m = pmax[s];
                    v += __shfl_xor_sync(0xffffffffu, v, 1);
                    v += __shfl_xor_sync(0xffffffffu, v, 2);
                    v2 += __shfl_xor_sync(0xffffffffu, v2, 1);
                    v2 += __shfl_xor_sync(0xffffffffu, v2, 2);
                    m = fmaxf(m, __shfl_xor_sync(0xffffffffu, m, 1));
                    m = fmaxf(m, __shfl_xor_sync(0xffffffffu, m, 2));
                    if (qcol == 0) {
                        int rl = wm * 64 + (s >> 1) * 16 + qrow + 8 * (s & 1);
                        int grow = cur_bm * 128 + rl;
                        atomicAdd(&g_rsum[grow], v);
                        atomicAdd(&g_rsum2[grow], v2);
                        atomicMax(&g_rmaxU[grow], encf(m));
                    }
                    psum[s] = 0.f; psum2[s] = 0.f; pmax[s] = -3.0e38f;
                }
            }
            // per-row constants
            if (tid < 128) {
                int g = bm * 128 + tid;
                int pair = g >> 1, side = g & 1;
                int a = readIdx(tp, 2LL * pair + side, is64);
                s_l[tid] = readIdx(tp, 2LL * pair, is64);
                s_r[tid] = readIdx(tp, 2LL * pair + 1, is64);
                s_cm[tid] = g_pos[pair] - g_sqn[a] + GAMMA_F;
                s_wa2[tid] = 2.0f * g_winv[a];
            }
            // A tile: thread handles row tid>>1, chunk-half tid&1
            {
                int r = tid >> 1, h = tid & 1;
                int g = bm * 128 + r;
                int pair = g >> 1, side = g & 1;
                int a = readIdx(tp, 2LL * pair + side, is64);
                const float4* src = (const float4*)&g_featP[(size_t)a * 128] + h * 16;
                int r7 = r & 7;
                float* dbase = sA + r * 128;
#pragma unroll
                for (int c = 0; c < 16; c++) {
                    int cc = h * 16 + c;
                    float4 v = src[c];
                    *(float4*)&dbase[(cc ^ r7) << 2] = v;
                }
            }
            cur_bm = bm;
        }

        // prefetch next B
        if (t + 1 < t1) {
            int chn = (int)((t + 1) % NCHUNK);
            int nb = chn * 128;
            uint32_t dst = sBaddr[b ^ 1];
#pragma unroll
            for (int q = 0; q < 16; q++) {
                int idx = tid + q * 256;
                int row = idx >> 5, cc = idx & 31;
                cp_async16(dst + row * 512 + (((uint32_t)(cc ^ (row & 7))) << 4),
                           &g_featP[(size_t)(nb + row) * 128 + cc * 4]);
            }
            if (tid < 32) cp_async16(sqnjaddr + (b ^ 1) * 512 + tid * 16, &g_sqn[nb + tid * 4]);
            else if (tid < 64) cp_async16(wjaddr + (b ^ 1) * 512 + (tid - 32) * 16, &g_winv[nb + (tid - 32) * 4]);
            cp_commit();
            asm volatile("cp.async.wait_group 1;" ::: "memory");
        } else {
            asm volatile("cp.async.wait_group 0;" ::: "memory");
        }
        __syncthreads();

        // ---- compute 128x128 chunk: 8 kgroups x (12 LDS.128 + 32 MMA) ----
        float acc[4][4][4];
#pragma unroll
        for (int mi = 0; mi < 4; mi++)
#pragma unroll
            for (int ni = 0; ni < 4; ni++)
#pragma unroll
                for (int c = 0; c < 4; c++) acc[mi][ni][c] = 0.f;

        const uint4* pA4 = (const uint4*)sA;
        const uint4* pB4 = (const uint4*)sBb[b];

#pragma unroll
        for (int kg = 0; kg < 8; kg++) {
            uint4 afr[4][2], bfr[4];
            const int kc = kg * 4 + qcol;
#pragma unroll
            for (int mi = 0; mi < 4; mi++) {
                int R = wm * 64 + mi * 16 + qrow;
                int cc = kc ^ (R & 7);
                afr[mi][0] = pA4[R * 32 + cc];
                afr[mi][1] = pA4[(R + 8) * 32 + cc];
            }
#pragma unroll
            for (int ni = 0; ni < 4; ni++) {
                int Nb = wn * 32 + ni * 8 + qrow;
                int cc = kc ^ (Nb & 7);
                bfr[ni] = pB4[Nb * 32 + cc];
            }
#pragma unroll
            for (int mi = 0; mi < 4; mi++) {
                uint32_t A0[4] = { afr[mi][0].x, afr[mi][1].x, afr[mi][0].y, afr[mi][1].y };
                uint32_t A1[4] = { afr[mi][0].z, afr[mi][1].z, afr[mi][0].w, afr[mi][1].w };
#pragma unroll
                for (int ni = 0; ni < 4; ni++) {
                    uint32_t B0[2] = { bfr[ni].x, bfr[ni].y };
                    uint32_t B1[2] = { bfr[ni].z, bfr[ni].w };
                    mma_tf32(acc[mi][ni], A0, B0);
                    mma_tf32(acc[mi][ni], A1, B1);
                }
            }
        }

        // ---- epilogue ----
        const int jc = ch * 128;
#pragma unroll
        for (int mi = 0; mi < 4; mi++) {
            int r0 = wm * 64 + mi * 16 + qrow, r1 = r0 + 8;
            float cm0 = s_cm[r0], cm1 = s_cm[r1];
            float tw0 = s_wa2[r0], tw1 = s_wa2[r1];
            int l0 = s_l[r0], rr0 = s_r[r0];
            int l1 = s_l[r1], rr1 = s_r[r1];
            size_t gY0 = (size_t)(cur_bm * 128 + r0) * NPAD + jc;
            size_t gY1 = (size_t)(cur_bm * 128 + r1) * NPAD + jc;
            const int s0 = mi * 2, s1 = mi * 2 + 1;
#pragma unroll
            for (int ni = 0; ni < 4; ni++) {
                int c = wn * 32 + ni * 8 + qcol * 2;
                int j0 = jc + c, j1 = j0 + 1;
                float sq0 = s_sqnj[b][c], sq1 = s_sqnj[b][c + 1];
                float wj0 = s_wj[b][c], wj1 = s_wj[b][c + 1];
                float m00 = 1.0f - (float)(j0 == l0) - (float)(j0 == rr0);
                float m01 = 1.0f - (float)(j1 == l0) - (float)(j1 == rr0);
                float m10 = 1.0f - (float)(j0 == l1) - (float)(j0 == rr1);
                float m11 = 1.0f - (float)(j1 == l1) - (float)(j1 == rr1);
                float y00 = fmaf(m00, cm0 + fmaf(tw0 * wj0, acc[mi][ni][0], -sq0), -cm0);
                float y01 = fmaf(m01, cm0 + fmaf(tw0 * wj1, acc[mi][ni][1], -sq1), -cm0);
                float y10 = fmaf(m10, cm1 + fmaf(tw1 * wj0, acc[mi][ni][2], -sq0), -cm1);
                float y11 = fmaf(m11, cm1 + fmaf(tw1 * wj1, acc[mi][ni][3], -sq1), -cm1);
                *(__half2*)(g_Y + gY0 + c) = __floats2half2_rn(y00, y01);
                *(__half2*)(g_Y + gY1 + c) = __floats2half2_rn(y10, y11);
                if (j0 < NODE) {
                    psum[s0] += y00; psum2[s0] += y00 * y00; pmax[s0] = fmaxf(pmax[s0], y00);
                    psum[s1] += y10; psum2[s1] += y10 * y10; pmax[s1] = fmaxf(pmax[s1], y10);
                }
                if (j1 < NODE) {
                    psum[s0] += y01; psum2[s0] += y01 * y01; pmax[s0] = fmaxf(pmax[s0], y01);
                    psum[s1] += y11; psum2[s1] += y11 * y11; pmax[s1] = fmaxf(pmax[s1], y11);
                }
            }
        }
        __syncthreads();   // protect sB[b]/s_sqnj[b]/s_wj[b] before refill
    }

    // final flush
#pragma unroll
    for (int s = 0; s < 8; s++) {
        float v = psum[s], v2 = psum2[s], m = pmax[s];
        v += __shfl_xor_sync(0xffffffffu, v, 1);
        v += __shfl_xor_sync(0xffffffffu, v, 2);
        v2 += __shfl_xor_sync(0xffffffffu, v2, 1);
        v2 += __shfl_xor_sync(0xffffffffu, v2, 2);
        m = fmaxf(m, __shfl_xor_sync(0xffffffffu, m, 1));
        m = fmaxf(m, __shfl_xor_sync(0xffffffffu, m, 2));
        if (qcol == 0) {
            int rl = wm * 64 + (s >> 1) * 16 + qrow + 8 * (s & 1);
            int grow = cur_bm * 128 + rl;
            atomicAdd(&g_rsum[grow], v);
            atomicAdd(&g_rsum2[grow], v2);
            atomicMax(&g_rmaxU[grow], encf(m));
        }
    }
}

// ---------------- launch 4: streaming logsumexp ----------------
__device__ float blockSum(float v) {
    __shared__ float scr[8];
    __shared__ float bc;
    v = warpSum(v);
    if ((threadIdx.x & 31) == 0) scr[threadIdx.x >> 5] = v;
    __syncthreads();
    if (threadIdx.x < 32) {
        float t = (threadIdx.x < 8) ? scr[threadIdx.x] : 0.f;
        t = warpSum(t);
        if (threadIdx.x == 0) bc = t;
    }
    __syncthreads();
    float r = bc;
    __syncthreads();
    return r;
}

__device__ __forceinline__ void unpack8(uint4 v, float* f) {
    float2 a = __half22float2(*(__half2*)&v.x);
    float2 b = __half22float2(*(__half2*)&v.y);
    float2 c = __half22float2(*(__half2*)&v.z);
    float2 d = __half22float2(*(__half2*)&v.w);
    f[0] = a.x; f[1] = a.y; f[2] = b.x; f[3] = b.y;
    f[4] = c.x; f[5] = c.y; f[6] = d.x; f[7] = d.y;
}

__global__ __launch_bounds__(256) void k_lse() {
    const int row = blockIdx.x;
    const int tid = threadIdx.x;
    float sum = g_rsum[row], sum2 = g_rsum2[row];
    float mx = decf(g_rmaxU[row]);
    float mean = sum * (1.0f / 30000.0f);
    float var = sum2 * (1.0f / 30000.0f) - mean * mean;
    float a = LAMB_F / sqrtf(var);
    const uint4* x4 = (const uint4*)(g_Y + (size_t)row * NPAD);
    float se = 0.f;
    for (int i = tid; i < 3750; i += 256) {   // 3750*8 = 30000 exactly
        float f[8];
        unpack8(x4[i], f);
#pragma unroll
        for (int c = 0; c < 8; c++) se += __expf(a * (f[c] - mx));
    }
    float setot = blockSum(se);
    if (tid == 0) {
        float lse = a * (mx - mean) + TAU_F + logf(setot);
        atomicAdd(&g_acc, (double)lse);
    }
}

__global__ void k_final(float* out) {
    if (threadIdx.x == 0 && blockIdx.x == 0)
        out[0] = (float)(g_acc / (double)NBATCH);
}

// ---------------- launch ----------------
extern "C" void kernel_launch(void* const* d_in, const int* in_sizes, int n_in,
                              void* d_out, int out_size) {
    const void* tp = nullptr;
    const void* adj = nullptr;
    const float* emb = nullptr;
    for (int i = 0; i < n_in; i++) {
        if (in_sizes[i] == NBATCH * 2)        tp  = d_in[i];
        else if (in_sizes[i] == 2 * NE)       adj = d_in[i];
        else if (in_sizes[i] == NODE * HID)   emb = (const float*)d_in[i];
    }
    float* out = (float*)d_out;

    k_zero<<<2048, 256>>>(tp, adj);                                   // idx 0
    k_scatter<<<(int)(((long long)NE * 32 + 255) / 256), 256>>>(adj, emb); // idx 1
    k_prep<<<NPAD / 8 + NBATCH / 8, 256>>>(tp);                       // idx 2

    cudaFuncSetAttribute(k_mma, cudaFuncAttributeMaxDynamicSharedMemorySize, 196608);
    k_mma<<<GRID_MMA, 256, 196608>>>(tp);                             // idx 3 (ncu)

    k_lse<<<AROWS, 256>>>();                                          // idx 4
    k_final<<<1, 1>>>(out);                                           // idx 5
}

// round 8
// speedup vs baseline: 4.0918x; 1.5874x over previous
#include <cuda_runtime.h>
#include <cuda_fp16.h>
#include <cuda_bf16.h>
#include <math.h>
#include <stdint.h>

#define NODE   30000
#define NPAD   30208          // 118 * 256
#define HID    128
#define NE     600000
#define NBATCH 4096
#define AROWS  8192
#define BN     256
#define NCHUNK 118            // NPAD/BN
#define NBM    64             // AROWS/128
#define TOTW   (NBM * NCHUNK) // 7552
#define GRID_MMA 148
#define GAMMA_F 3.0f
#define LAMB_F  30.0f
#define TAU_F   10.0f

// ---------------- device globals ----------------
__device__ float  g_feat[(size_t)NPAD * HID];    // raw aggregated (unnormalized) fp32
__device__ __nv_bfloat16 g_featB[(size_t)NPAD * HID]; // normalized bf16 (7.7MB, L2-resident)
__device__ float  g_deg[NODE];
__device__ float  g_sqn[NPAD];                   // ||w*feat||^2 fp32
__device__ float  g_pos[NBATCH];
__device__ __half g_Y[(size_t)AROWS * NPAD];     // unmasked y = 2*dot - sqn_j, fp16
__device__ float  g_rsum[AROWS], g_rsum2[AROWS];
__device__ unsigned g_rmaxU[AROWS];
__device__ double g_acc;
__device__ int    g_tp64, g_adj64;

__device__ __forceinline__ int readIdx(const void* p, long long i, int is64) {
    if (is64) return (int)((const long long*)p)[i];
    return ((const int*)p)[i];
}
__device__ __forceinline__ uint32_t smem_u32(const void* p) {
    uint32_t a;
    asm("{ .reg .u64 t; cvta.to.shared.u64 t, %1; cvt.u32.u64 %0, t; }" : "=r"(a) : "l"(p));
    return a;
}
__device__ __forceinline__ void cp_async16(uint32_t s, const void* g) {
    asm volatile("cp.async.cg.shared.global [%0], [%1], 16;" :: "r"(s), "l"(g));
}
__device__ __forceinline__ void cp_commit() {
    asm volatile("cp.async.commit_group;" ::: "memory");
}
__device__ __forceinline__ void ldsm4(uint32_t* r, uint32_t addr) {
    asm volatile("ldmatrix.sync.aligned.m8n8.x4.shared.b16 {%0,%1,%2,%3}, [%4];"
        : "=r"(r[0]), "=r"(r[1]), "=r"(r[2]), "=r"(r[3]) : "r"(addr));
}
__device__ __forceinline__ void mma_bf16(float* d, const uint32_t* a, const uint32_t* b) {
    asm volatile(
        "mma.sync.aligned.m16n8k16.row.col.f32.bf16.bf16.f32 "
        "{%0,%1,%2,%3}, {%4,%5,%6,%7}, {%8,%9}, {%0,%1,%2,%3};"
        : "+f"(d[0]), "+f"(d[1]), "+f"(d[2]), "+f"(d[3])
        : "r"(a[0]), "r"(a[1]), "r"(a[2]), "r"(a[3]), "r"(b[0]), "r"(b[1]));
}
__device__ __forceinline__ unsigned encf(float f) {
    unsigned u = __float_as_uint(f);
    return (u & 0x80000000u) ? ~u : (u | 0x80000000u);
}
__device__ __forceinline__ float decf(unsigned e) {
    return (e & 0x80000000u) ? __uint_as_float(e & 0x7FFFFFFFu) : __uint_as_float(~e);
}

// ---------------- launch 0: zero + dtype detect ----------------
__global__ void k_zero(const void* tp, const void* adj) {
    size_t i = (size_t)blockIdx.x * blockDim.x + threadIdx.x;
    size_t stride = (size_t)gridDim.x * blockDim.x;
    float4 z = make_float4(0.f, 0.f, 0.f, 0.f);
    float4* f4 = (float4*)g_feat;
    size_t n4 = (size_t)NPAD * HID / 4;
    for (size_t j = i; j < n4; j += stride) f4[j] = z;
    for (size_t j = i; j < NODE; j += stride) g_deg[j] = 0.f;
    for (size_t j = i; j < AROWS; j += stride) {
        g_rsum[j] = 0.f; g_rsum2[j] = 0.f; g_rmaxU[j] = encf(-3.0e38f);
    }
    if (i == 0) {
        g_acc = 0.0;
        const int* a = (const int*)tp;
        int all0 = 1;
        for (int k = 0; k < 16; k++) if (a[2 * k + 1] != 0) all0 = 0;
        g_tp64 = all0;
        const int* b = (const int*)adj;
        all0 = 1;
        for (int k = 0; k < 16; k++) if (b[2 * k + 1] != 0) all0 = 0;
        g_adj64 = all0;
    }
}

// ---------------- launch 1: scatter raw emb + degree ----------------
__global__ void k_scatter(const void* adj, const float* emb) {
    long long idx = (long long)blockIdx.x * blockDim.x + threadIdx.x;
    if (idx >= (long long)NE * 32) return;
    int e = (int)(idx >> 5);
    int lane = (int)(idx & 31);
    int is64 = g_adj64;
    int r = readIdx(adj, e, is64);
    int c = readIdx(adj, (long long)NE + e, is64);
    if (lane == 0) atomicAdd(&g_deg[r], 1.0f);
    float4 v = ((const float4*)emb)[(size_t)c * 32 + lane];
    atomicAdd(((float4*)g_feat) + (size_t)r * 32 + lane, v);
}

__device__ __forceinline__ float warpSum(float v) {
    for (int o = 16; o; o >>= 1) v += __shfl_xor_sync(0xffffffffu, v, o);
    return v;
}

// ---------------- launch 2: normalize -> bf16, sqn, pos ----------------
// blocks [0, NPAD/8): warp per row; blocks [NPAD/8, +NBATCH/8): warp per pair
__global__ __launch_bounds__(256) void k_prep(const void* tp) {
    const int tid = threadIdx.x, lane = tid & 31, w = tid >> 5;
    const int blk = blockIdx.x;
    if (blk < NPAD / 8) {
        int row = blk * 8 + w;
        float4 v = ((const float4*)g_feat)[(size_t)row * 32 + lane];
        float wgt = 1.0f;
        if (row < NODE) {
            float d = g_deg[row];
            wgt = (d > 0.f) ? (1.0f / d) : 1.0f;
        }
        float x0 = v.x * wgt, x1 = v.y * wgt, x2 = v.z * wgt, x3 = v.w * wgt;
        float s = x0 * x0 + x1 * x1 + x2 * x2 + x3 * x3;
        float stot = warpSum(s);
        if (lane == 0) g_sqn[row] = stot;
        __nv_bfloat162 p0 = __float22bfloat162_rn(make_float2(x0, x1));
        __nv_bfloat162 p1 = __float22bfloat162_rn(make_float2(x2, x3));
        uint2 u;
        u.x = *(uint32_t*)&p0;
        u.y = *(uint32_t*)&p1;
        ((uint2*)(g_featB + (size_t)row * HID))[lane] = u;
    } else {
        int pr = (blk - NPAD / 8) * 8 + w;
        int is64 = g_tp64;
        int l = readIdx(tp, 2LL * pr, is64);
        int r = readIdx(tp, 2LL * pr + 1, is64);
        float dl = g_deg[l], dr = g_deg[r];
        float wl = (dl > 0.f) ? (1.0f / dl) : 1.0f;
        float wr = (dr > 0.f) ? (1.0f / dr) : 1.0f;
        float4 a = ((const float4*)g_feat)[(size_t)l * 32 + lane];
        float4 b = ((const float4*)g_feat)[(size_t)r * 32 + lane];
        float dx = wl * a.x - wr * b.x, dy = wl * a.y - wr * b.y;
        float dz = wl * a.z - wr * b.z, dw = wl * a.w - wr * b.w;
        float s = warpSum(dx * dx + dy * dy + dz * dz + dw * dw);
        if (lane == 0) g_pos[pr] = s;
    }
}

// ---------------- launch 3: persistent bf16 GEMM + fused epilogue+stats ----
// 148 persistent CTAs, 512 threads (16 warps, 4m x 4n, warp tile 32x64).
// Chunk = 128 A-rows x 256 cols, K=128. A (gathered, bf16) persistent in smem,
// B double-buffered via cp.async. All fragments via conflict-free swizzled
// ldmatrix. Epilogue: y = 2*dot - sqn_j (UNMASKED; mask applied analytically
// in k_lse), fp16 store + per-row sum/sum2/max in registers.
__global__ __launch_bounds__(512, 1) void k_mma(const void* tp) {
    extern __shared__ char dsm[];
    char* pA = dsm;                           // 128*256B = 32KB
    char* pB[2] = { dsm + 32768, dsm + 98304 };   // 2 x 64KB
    __shared__ float s_sqnj[2][BN];

    const int tid = threadIdx.x;
    const int lane = tid & 31, warp = tid >> 5;
    const int wm = warp >> 2, wn = warp & 3;
    const int qrow = lane >> 2, qcol = lane & 3;
    const int is64 = g_tp64;
    const uint32_t sAaddr = smem_u32(pA);
    const uint32_t sBaddr[2] = { smem_u32(pB[0]), smem_u32(pB[1]) };
    const uint32_t sqnjaddr = smem_u32(s_sqnj);

    // ldmatrix lane address components
    const int aRow0 = wm * 32 + (lane & 15);          // + mi*16
    const int aKh   = (lane >> 4) & 1;
    const int bRowL = (lane & 7) + (((lane >> 4) & 1) << 3);   // + wn*64 + nt*16
    const int bKh   = (lane >> 3) & 1;

    const long long t0 = ((long long)blockIdx.x * TOTW) / GRID_MMA;
    const long long t1 = ((long long)(blockIdx.x + 1) * TOTW) / GRID_MMA;
    if (t0 >= t1) return;

    int cur_bm = -1;
    float psum[4], psum2[4], pmax[4];
#pragma unroll
    for (int s = 0; s < 4; s++) { psum[s] = 0.f; psum2[s] = 0.f; pmax[s] = -3.0e38f; }

    // prefetch B + sqn for first work item (group committed before A's group)
    {
        int nb = (int)(t0 % NCHUNK) * BN;
#pragma unroll
        for (int q = 0; q < 8; q++) {
            int idx = tid + q * 512;             // 0..4095
            int row = idx >> 4, cc = idx & 15;
            cp_async16(sBaddr[0] + row * 256 + ((cc ^ (row & 7)) << 4),
                       g_featB + (size_t)(nb + row) * HID + cc * 8);
        }
        if (tid < 64) cp_async16(sqnjaddr + tid * 16, &g_sqn[nb + tid * 4]);
        cp_commit();
    }

    for (long long t = t0; t < t1; t++) {
        const int b = (int)((t - t0) & 1);
        const int bm = (int)(t / NCHUNK);
        const int ch = (int)(t % NCHUNK);

        if (bm != cur_bm) {
            if (cur_bm >= 0) {   // flush stats of previous bm
#pragma unroll
                for (int s = 0; s < 4; s++) {
                    float v = psum[s], v2 = psum2[s], m = pmax[s];
                    v += __shfl_xor_sync(0xffffffffu, v, 1);
                    v += __shfl_xor_sync(0xffffffffu, v, 2);
                    v2 += __shfl_xor_sync(0xffffffffu, v2, 1);
                    v2 += __shfl_xor_sync(0xffffffffu, v2, 2);
                    m = fmaxf(m, __shfl_xor_sync(0xffffffffu, m, 1));
                    m = fmaxf(m, __shfl_xor_sync(0xffffffffu, m, 2));
                    if (qcol == 0) {
                        int grow = cur_bm * 128 + wm * 32 + (s >> 1) * 16 + qrow + 8 * (s & 1);
                        atomicAdd(&g_rsum[grow], v);
                        atomicAdd(&g_rsum2[grow], v2);
                        atomicMax(&g_rmaxU[grow], encf(m));
                    }
                    psum[s] = 0.f; psum2[s] = 0.f; pmax[s] = -3.0e38f;
                }
            }
            // A tile: 128 gathered rows, bf16, swizzled; 2048 chunks of 16B
#pragma unroll
            for (int q = 0; q < 4; q++) {
                int idx = tid + q * 512;         // 0..2047
                int row = idx >> 4, cc = idx & 15;
                int g = bm * 128 + row;
                int pair = g >> 1, side = g & 1;
                int arow = readIdx(tp, 2LL * pair + side, is64);
                cp_async16(sAaddr + row * 256 + ((cc ^ (row & 7)) << 4),
                           g_featB + (size_t)arow * HID + cc * 8);
            }
            cp_commit();
            cur_bm = bm;
        }

        // prefetch next B
        if (t + 1 < t1) {
            int nb = (int)((t + 1) % NCHUNK) * BN;
            uint32_t dst = sBaddr[b ^ 1];
#pragma unroll
            for (int q = 0; q < 8; q++) {
                int idx = tid + q * 512;
                int row = idx >> 4, cc = idx & 15;
                cp_async16(dst + row * 256 + ((cc ^ (row & 7)) << 4),
                           g_featB + (size_t)(nb + row) * HID + cc * 8);
            }
            if (tid < 64) cp_async16(sqnjaddr + (b ^ 1) * (BN * 4) + tid * 16, &g_sqn[nb + tid * 4]);
            cp_commit();
            asm volatile("cp.async.wait_group 1;" ::: "memory");
        } else {
            asm volatile("cp.async.wait_group 0;" ::: "memory");
        }
        __syncthreads();

        // ---- compute 128x256 chunk: 8 kgroups x (6 LDSM.x4 + 16 HMMA) ----
        float acc[2][8][4];
#pragma unroll
        for (int mi = 0; mi < 2; mi++)
#pragma unroll
            for (int ni = 0; ni < 8; ni++)
#pragma unroll
                for (int c = 0; c < 4; c++) acc[mi][ni][c] = 0.f;

        const uint32_t sB = sBaddr[b];
#pragma unroll
        for (int kg = 0; kg < 8; kg++) {
            uint32_t af[2][4], bf[4][4];
            const int kcA = 2 * kg + aKh;
            const int kcB = 2 * kg + bKh;
#pragma unroll
            for (int mi = 0; mi < 2; mi++) {
                int row = aRow0 + mi * 16;
                ldsm4(af[mi], sAaddr + row * 256 + ((kcA ^ (row & 7)) << 4));
            }
#pragma unroll
            for (int nt = 0; nt < 4; nt++) {
                int row = wn * 64 + nt * 16 + bRowL;
                ldsm4(bf[nt], sB + row * 256 + ((kcB ^ (row & 7)) << 4));
            }
#pragma unroll
            for (int mi = 0; mi < 2; mi++)
#pragma unroll
                for (int ni = 0; ni < 8; ni++) {
                    uint32_t bb[2] = { bf[ni >> 1][(ni & 1) * 2], bf[ni >> 1][(ni & 1) * 2 + 1] };
                    mma_bf16(acc[mi][ni], af[mi], bb);
                }
        }

        // ---- epilogue: y = 2*acc - sqn_j (unmasked) ----
        const int jc = ch * BN;
#pragma unroll
        for (int mi = 0; mi < 2; mi++) {
            int r0 = wm * 32 + mi * 16 + qrow, r1 = r0 + 8;
            size_t gY0 = (size_t)(cur_bm * 128 + r0) * NPAD + jc;
            size_t gY1 = (size_t)(cur_bm * 128 + r1) * NPAD + jc;
            const int s0 = mi * 2, s1 = mi * 2 + 1;
#pragma unroll
            for (int ni = 0; ni < 8; ni++) {
                int c = wn * 64 + ni * 8 + qcol * 2;
                float sq0 = s_sqnj[b][c], sq1 = s_sqnj[b][c + 1];
                float y00 = fmaf(2.f, acc[mi][ni][0], -sq0);
                float y01 = fmaf(2.f, acc[mi][ni][1], -sq1);
                float y10 = fmaf(2.f, acc[mi][ni][2], -sq0);
                float y11 = fmaf(2.f, acc[mi][ni][3], -sq1);
                *(__half2*)(g_Y + gY0 + c) = __floats2half2_rn(y00, y01);
                *(__half2*)(g_Y + gY1 + c) = __floats2half2_rn(y10, y11);
                if (jc + c < NODE) {   // pairs aligned, NODE even
                    psum[s0] += y00 + y01;
                    psum2[s0] += y00 * y00 + y01 * y01;
                    pmax[s0] = fmaxf(pmax[s0], fmaxf(y00, y01));
                    psum[s1] += y10 + y11;
                    psum2[s1] += y10 * y10 + y11 * y11;
                    pmax[s1] = fmaxf(pmax[s1], fmaxf(y10, y11));
                }
            }
        }
        __syncthreads();
    }

    // final flush
#pragma unroll
    for (int s = 0; s < 4; s++) {
        float v = psum[s], v2 = psum2[s], m = pmax[s];
        v += __shfl_xor_sync(0xffffffffu, v, 1);
        v += __shfl_xor_sync(0xffffffffu, v, 2);
        v2 += __shfl_xor_sync(0xffffffffu, v2, 1);
        v2 += __shfl_xor_sync(0xffffffffu, v2, 2);
        m = fmaxf(m, __shfl_xor_sync(0xffffffffu, m, 1));
        m = fmaxf(m, __shfl_xor_sync(0xffffffffu, m, 2));
        if (qcol == 0) {
            int grow = cur_bm * 128 + wm * 32 + (s >> 1) * 16 + qrow + 8 * (s & 1);
            atomicAdd(&g_rsum[grow], v);
            atomicAdd(&g_rsum2[grow], v2);
            atomicMax(&g_rmaxU[grow], encf(m));
        }
    }
}

// ---------------- launch 4: logsumexp with analytic mask correction --------
__device__ float blockSum(float v) {
    __shared__ float scr[8];
    __shared__ float bc;
    v = warpSum(v);
    if ((threadIdx.x & 31) == 0) scr[threadIdx.x >> 5] = v;
    __syncthreads();
    if (threadIdx.x < 32) {
        float t = (threadIdx.x < 8) ? scr[threadIdx.x] : 0.f;
        t = warpSum(t);
        if (threadIdx.x == 0) bc = t;
    }
    __syncthreads();
    float r = bc;
    __syncthreads();
    return r;
}

__device__ __forceinline__ void unpack8(uint4 v, float* f) {
    float2 a = __half22float2(*(__half2*)&v.x);
    float2 b = __half22float2(*(__half2*)&v.y);
    float2 c = __half22float2(*(__half2*)&v.z);
    float2 d = __half22float2(*(__half2*)&v.w);
    f[0] = a.x; f[1] = a.y; f[2] = b.x; f[3] = b.y;
    f[4] = c.x; f[5] = c.y; f[6] = d.x; f[7] = d.y;
}

__global__ __launch_bounds__(256) void k_lse(const void* tp) {
    const int row = blockIdx.x;
    const int tid = threadIdx.x;
    const int pair = row >> 1, side = row & 1;
    const int is64 = g_tp64;
    const int l = readIdx(tp, 2LL * pair, is64);
    const int r = readIdx(tp, 2LL * pair + 1, is64);
    const float pos = g_pos[pair];
    const float sqa = g_sqn[side ? r : l];
    const float cm = pos - sqa + GAMMA_F;

    // analytic unmasked values at masked columns (exact identities):
    //   a==col      -> y_old = sqa ;  a!=col (partner) -> y_old = sqa - pos
    float yol, yor, ynl, ynr;
    float sum = g_rsum[row], sum2 = g_rsum2[row];
    if (l != r) {
        yol = side ? (sqa - pos) : sqa;
        yor = side ? sqa : (sqa - pos);
        ynl = -cm; ynr = -cm;
        sum += (ynl - yol) + (ynr - yor);
        sum2 += (ynl * ynl - yol * yol) + (ynr * ynr - yor * yor);
    } else {
        yol = sqa;
        ynl = -yol - 2.0f * cm;       // mask = -1 when l == r
        yor = 0.f; ynr = 0.f;         // unused
        sum += ynl - yol;
        sum2 += ynl * ynl - yol * yol;
    }
    const float mean = sum * (1.0f / 30000.0f);
    const float var = sum2 * (1.0f / 30000.0f) - mean * mean;
    const float a = LAMB_F / sqrtf(var);
    const float mx = decf(g_rmaxU[row]);

    const uint4* x4 = (const uint4*)(g_Y + (size_t)row * NPAD);
    float se = 0.f;
    for (int i = tid; i < 3750; i += 256) {   // 3750*8 = 30000
        float f[8];
        unpack8(x4[i], f);
#pragma unroll
        for (int c = 0; c < 8; c++) se += __expf(a * (f[c] - mx));
    }
    float setot = blockSum(se);
    if (tid == 0) {
        // swap stale unmasked contributions for masked ones
        setot += __expf(a * (ynl - mx)) - __expf(a * (yol - mx));
        if (l != r) setot += __expf(a * (ynr - mx)) - __expf(a * (yor - mx));
        float lse = a * (mx - mean) + TAU_F + logf(setot);
        atomicAdd(&g_acc, (double)lse);
    }
}

__global__ void k_final(float* out) {
    if (threadIdx.x == 0 && blockIdx.x == 0)
        out[0] = (float)(g_acc / (double)NBATCH);
}

// ---------------- launch ----------------
extern "C" void kernel_launch(void* const* d_in, const int* in_sizes, int n_in,
                              void* d_out, int out_size) {
    const void* tp = nullptr;
    const void* adj = nullptr;
    const float* emb = nullptr;
    for (int i = 0; i < n_in; i++) {
        if (in_sizes[i] == NBATCH * 2)        tp  = d_in[i];
        else if (in_sizes[i] == 2 * NE)       adj = d_in[i];
        else if (in_sizes[i] == NODE * HID)   emb = (const float*)d_in[i];
    }
    float* out = (float*)d_out;

    k_zero<<<2048, 256>>>(tp, adj);                                        // idx 0
    k_scatter<<<(int)(((long long)NE * 32 + 255) / 256), 256>>>(adj, emb); // idx 1
    k_prep<<<NPAD / 8 + NBATCH / 8, 256>>>(tp);                            // idx 2

    // dynamic smem: A 32KB + 2 x B 64KB = 160KB
    cudaFuncSetAttribute(k_mma, cudaFuncAttributeMaxDynamicSharedMemorySize, 163840);
    k_mma<<<GRID_MMA, 512, 163840>>>(tp);                                  // idx 3 (ncu)

    k_lse<<<AROWS, 256>>>(tp);                                             // idx 4
    k_final<<<1, 1>>>(out);                                                // idx 5
}

// round 9
// speedup vs baseline: 4.4499x; 1.0875x over previous
#include <cuda_runtime.h>
#include <cuda_fp16.h>
#include <cuda_bf16.h>
#include <math.h>
#include <stdint.h>

#define NODE   30000
#define NPAD   30080          // 235 * 128
#define HID    128
#define NE     600000
#define NBATCH 4096
#define AROWS  8192
#define BN     128
#define NCHUNK 235            // NPAD/BN
#define NBM    64             // AROWS/128
#define TOTW   (NBM * NCHUNK) // 15040
#define GRID_MMA 296          // 2 CTAs per SM
#define GAMMA_F 3.0f
#define LAMB_F  30.0f
#define TAU_F   10.0f

// ---------------- device globals ----------------
__device__ float  g_feat[(size_t)NPAD * HID];    // raw aggregated (unnormalized) fp32
__device__ __nv_bfloat16 g_featB[(size_t)NPAD * HID]; // normalized bf16 (7.7MB)
__device__ float  g_deg[NODE];
__device__ float  g_sqn[NPAD];
__device__ float  g_pos[NBATCH];
__device__ __half g_Y[(size_t)AROWS * NPAD];     // unmasked y = 2*dot - sqn_j, fp16
__device__ float  g_rsum[AROWS], g_rsum2[AROWS];
__device__ unsigned g_rmaxU[AROWS];
__device__ double g_acc;
__device__ int    g_tp64, g_adj64;

__device__ __forceinline__ int readIdx(const void* p, long long i, int is64) {
    if (is64) return (int)((const long long*)p)[i];
    return ((const int*)p)[i];
}
__device__ __forceinline__ uint32_t smem_u32(const void* p) {
    uint32_t a;
    asm("{ .reg .u64 t; cvta.to.shared.u64 t, %1; cvt.u32.u64 %0, t; }" : "=r"(a) : "l"(p));
    return a;
}
__device__ __forceinline__ void cp_async16(uint32_t s, const void* g) {
    asm volatile("cp.async.cg.shared.global [%0], [%1], 16;" :: "r"(s), "l"(g));
}
__device__ __forceinline__ void cp_commit() {
    asm volatile("cp.async.commit_group;" ::: "memory");
}
__device__ __forceinline__ void ldsm4(uint32_t* r, uint32_t addr) {
    asm volatile("ldmatrix.sync.aligned.m8n8.x4.shared.b16 {%0,%1,%2,%3}, [%4];"
        : "=r"(r[0]), "=r"(r[1]), "=r"(r[2]), "=r"(r[3]) : "r"(addr));
}
__device__ __forceinline__ void mma_bf16(float* d, const uint32_t* a, const uint32_t* b) {
    asm volatile(
        "mma.sync.aligned.m16n8k16.row.col.f32.bf16.bf16.f32 "
        "{%0,%1,%2,%3}, {%4,%5,%6,%7}, {%8,%9}, {%0,%1,%2,%3};"
        : "+f"(d[0]), "+f"(d[1]), "+f"(d[2]), "+f"(d[3])
        : "r"(a[0]), "r"(a[1]), "r"(a[2]), "r"(a[3]), "r"(b[0]), "r"(b[1]));
}
__device__ __forceinline__ unsigned encf(float f) {
    unsigned u = __float_as_uint(f);
    return (u & 0x80000000u) ? ~u : (u | 0x80000000u);
}
__device__ __forceinline__ float decf(unsigned e) {
    return (e & 0x80000000u) ? __uint_as_float(e & 0x7FFFFFFFu) : __uint_as_float(~e);
}

// ---------------- launch 0: zero + dtype detect ----------------
__global__ void k_zero(const void* tp, const void* adj) {
    size_t i = (size_t)blockIdx.x * blockDim.x + threadIdx.x;
    size_t stride = (size_t)gridDim.x * blockDim.x;
    float4 z = make_float4(0.f, 0.f, 0.f, 0.f);
    float4* f4 = (float4*)g_feat;
    size_t n4 = (size_t)NPAD * HID / 4;
    for (size_t j = i; j < n4; j += stride) f4[j] = z;
    for (size_t j = i; j < NODE; j += stride) g_deg[j] = 0.f;
    for (size_t j = i; j < AROWS; j += stride) {
        g_rsum[j] = 0.f; g_rsum2[j] = 0.f; g_rmaxU[j] = encf(-3.0e38f);
    }
    if (i == 0) {
        g_acc = 0.0;
        const int* a = (const int*)tp;
        int all0 = 1;
        for (int k = 0; k < 16; k++) if (a[2 * k + 1] != 0) all0 = 0;
        g_tp64 = all0;
        const int* b = (const int*)adj;
        all0 = 1;
        for (int k = 0; k < 16; k++) if (b[2 * k + 1] != 0) all0 = 0;
        g_adj64 = all0;
    }
}

// ---------------- launch 1: scatter raw emb + degree ----------------
__global__ void k_scatter(const void* adj, const float* emb) {
    long long idx = (long long)blockIdx.x * blockDim.x + threadIdx.x;
    if (idx >= (long long)NE * 32) return;
    int e = (int)(idx >> 5);
    int lane = (int)(idx & 31);
    int is64 = g_adj64;
    int r = readIdx(adj, e, is64);
    int c = readIdx(adj, (long long)NE + e, is64);
    if (lane == 0) atomicAdd(&g_deg[r], 1.0f);
    float4 v = ((const float4*)emb)[(size_t)c * 32 + lane];
    atomicAdd(((float4*)g_feat) + (size_t)r * 32 + lane, v);
}

__device__ __forceinline__ float warpSum(float v) {
    for (int o = 16; o; o >>= 1) v += __shfl_xor_sync(0xffffffffu, v, o);
    return v;
}

// ---------------- launch 2: normalize -> bf16, sqn, pos ----------------
__global__ __launch_bounds__(256) void k_prep(const void* tp) {
    const int tid = threadIdx.x, lane = tid & 31, w = tid >> 5;
    const int blk = blockIdx.x;
    if (blk < NPAD / 8) {
        int row = blk * 8 + w;
        float4 v = ((const float4*)g_feat)[(size_t)row * 32 + lane];
        float wgt = 1.0f;
        if (row < NODE) {
            float d = g_deg[row];
            wgt = (d > 0.f) ? (1.0f / d) : 1.0f;
        }
        float x0 = v.x * wgt, x1 = v.y * wgt, x2 = v.z * wgt, x3 = v.w * wgt;
        float s = x0 * x0 + x1 * x1 + x2 * x2 + x3 * x3;
        float stot = warpSum(s);
        if (lane == 0) g_sqn[row] = stot;
        __nv_bfloat162 p0 = __float22bfloat162_rn(make_float2(x0, x1));
        __nv_bfloat162 p1 = __float22bfloat162_rn(make_float2(x2, x3));
        uint2 u;
        u.x = *(uint32_t*)&p0;
        u.y = *(uint32_t*)&p1;
        ((uint2*)(g_featB + (size_t)row * HID))[lane] = u;
    } else {
        int pr = (blk - NPAD / 8) * 8 + w;
        int is64 = g_tp64;
        int l = readIdx(tp, 2LL * pr, is64);
        int r = readIdx(tp, 2LL * pr + 1, is64);
        float dl = g_deg[l], dr = g_deg[r];
        float wl = (dl > 0.f) ? (1.0f / dl) : 1.0f;
        float wr = (dr > 0.f) ? (1.0f / dr) : 1.0f;
        float4 a = ((const float4*)g_feat)[(size_t)l * 32 + lane];
        float4 b = ((const float4*)g_feat)[(size_t)r * 32 + lane];
        float dx = wl * a.x - wr * b.x, dy = wl * a.y - wr * b.y;
        float dz = wl * a.z - wr * b.z, dw = wl * a.w - wr * b.w;
        float s = warpSum(dx * dx + dy * dy + dz * dz + dw * dw);
        if (lane == 0) g_pos[pr] = s;
    }
}

// ---------------- launch 3: persistent bf16 GEMM, 2 CTAs/SM ping-pong -----
// 296 CTAs x 256 threads (8 warps, 2m x 4n, warp tile 64x32). Chunk = 128
// A-rows x 128 cols, K=128. A persistent in smem per bm; B double-buffered.
// Two CTAs co-resident per SM so one CTA's epilogue overlaps the other's MMA.
// Epilogue: y = 2*dot - sqn_j (mask applied analytically in k_lse).
__global__ __launch_bounds__(256, 2) void k_mma(const void* tp) {
    extern __shared__ char dsm[];
    char* pA = dsm;                                // 32KB
    char* pB[2] = { dsm + 32768, dsm + 65536 };    // 2 x 32KB
    __shared__ float s_sqnj[2][BN];

    const int tid = threadIdx.x;
    const int lane = tid & 31, warp = tid >> 5;
    const int wm = warp >> 2, wn = warp & 3;       // 2m x 4n
    const int qrow = lane >> 2, qcol = lane & 3;
    const int is64 = g_tp64;
    const uint32_t sAaddr = smem_u32(pA);
    const uint32_t sBaddr[2] = { smem_u32(pB[0]), smem_u32(pB[1]) };
    const uint32_t sqnjaddr = smem_u32(s_sqnj);

    // ldmatrix lane address components
    const int aRow0 = wm * 64 + (lane & 15);       // + mi*16
    const int aKh   = (lane >> 4) & 1;
    const int bRowL = (lane & 7) + (((lane >> 4) & 1) << 3);   // + wn*32 + nt*16
    const int bKh   = (lane >> 3) & 1;

    const long long t0 = ((long long)blockIdx.x * TOTW) / GRID_MMA;
    const long long t1 = ((long long)(blockIdx.x + 1) * TOTW) / GRID_MMA;
    if (t0 >= t1) return;

    int cur_bm = -1;
    float psum[8], psum2[8], pmax[8];
#pragma unroll
    for (int s = 0; s < 8; s++) { psum[s] = 0.f; psum2[s] = 0.f; pmax[s] = -3.0e38f; }

    // prefetch B + sqn for first work item
    {
        int nb = (int)(t0 % NCHUNK) * BN;
#pragma unroll
        for (int q = 0; q < 8; q++) {
            int idx = tid + q * 256;               // 0..2047
            int row = idx >> 4, cc = idx & 15;
            cp_async16(sBaddr[0] + row * 256 + ((cc ^ (row & 7)) << 4),
                       g_featB + (size_t)(nb + row) * HID + cc * 8);
        }
        if (tid < 32) cp_async16(sqnjaddr + tid * 16, &g_sqn[nb + tid * 4]);
        cp_commit();
    }

    for (long long t = t0; t < t1; t++) {
        const int b = (int)((t - t0) & 1);
        const int bm = (int)(t / NCHUNK);
        const int ch = (int)(t % NCHUNK);

        if (bm != cur_bm) {
            if (cur_bm >= 0) {   // flush stats of previous bm
#pragma unroll
                for (int s = 0; s < 8; s++) {
                    float v = psum[s], v2 = psum2[s], m = pmax[s];
                    v += __shfl_xor_sync(0xffffffffu, v, 1);
                    v += __shfl_xor_sync(0xffffffffu, v, 2);
                    v2 += __shfl_xor_sync(0xffffffffu, v2, 1);
                    v2 += __shfl_xor_sync(0xffffffffu, v2, 2);
                    m = fmaxf(m, __shfl_xor_sync(0xffffffffu, m, 1));
                    m = fmaxf(m, __shfl_xor_sync(0xffffffffu, m, 2));
                    if (qcol == 0) {
                        int grow = cur_bm * 128 + wm * 64 + (s >> 1) * 16 + qrow + 8 * (s & 1);
                        atomicAdd(&g_rsum[grow], v);
                        atomicAdd(&g_rsum2[grow], v2);
                        atomicMax(&g_rmaxU[grow], encf(m));
                    }
                    psum[s] = 0.f; psum2[s] = 0.f; pmax[s] = -3.0e38f;
                }
            }
            // A tile: 128 gathered rows, bf16, swizzled; 2048 chunks of 16B
#pragma unroll
            for (int q = 0; q < 8; q++) {
                int idx = tid + q * 256;
                int row = idx >> 4, cc = idx & 15;
                int g = bm * 128 + row;
                int pair = g >> 1, side = g & 1;
                int arow = readIdx(tp, 2LL * pair + side, is64);
                cp_async16(sAaddr + row * 256 + ((cc ^ (row & 7)) << 4),
                           g_featB + (size_t)arow * HID + cc * 8);
            }
            cp_commit();
            cur_bm = bm;
        }

        // prefetch next B
        if (t + 1 < t1) {
            int nb = (int)((t + 1) % NCHUNK) * BN;
            uint32_t dst = sBaddr[b ^ 1];
#pragma unroll
            for (int q = 0; q < 8; q++) {
                int idx = tid + q * 256;
                int row = idx >> 4, cc = idx & 15;
                cp_async16(dst + row * 256 + ((cc ^ (row & 7)) << 4),
                           g_featB + (size_t)(nb + row) * HID + cc * 8);
            }
            if (tid < 32) cp_async16(sqnjaddr + (b ^ 1) * (BN * 4) + tid * 16, &g_sqn[nb + tid * 4]);
            cp_commit();
            asm volatile("cp.async.wait_group 1;" ::: "memory");
        } else {
            asm volatile("cp.async.wait_group 0;" ::: "memory");
        }
        __syncthreads();

        // ---- compute 128x128 chunk: 8 kgroups x (6 LDSM.x4 + 16 HMMA) ----
        float acc[4][4][4];
#pragma unroll
        for (int mi = 0; mi < 4; mi++)
#pragma unroll
            for (int ni = 0; ni < 4; ni++)
#pragma unroll
                for (int c = 0; c < 4; c++) acc[mi][ni][c] = 0.f;

        const uint32_t sB = sBaddr[b];
#pragma unroll
        for (int kg = 0; kg < 8; kg++) {
            uint32_t af[4][4], bf[2][4];
            const int kcA = 2 * kg + aKh;
            const int kcB = 2 * kg + bKh;
#pragma unroll
            for (int mi = 0; mi < 4; mi++) {
                int row = aRow0 + mi * 16;
                ldsm4(af[mi], sAaddr + row * 256 + ((kcA ^ (row & 7)) << 4));
            }
#pragma unroll
            for (int nt = 0; nt < 2; nt++) {
                int row = wn * 32 + nt * 16 + bRowL;
                ldsm4(bf[nt], sB + row * 256 + ((kcB ^ (row & 7)) << 4));
            }
#pragma unroll
            for (int mi = 0; mi < 4; mi++)
#pragma unroll
                for (int ni = 0; ni < 4; ni++) {
                    uint32_t bb[2] = { bf[ni >> 1][(ni & 1) * 2], bf[ni >> 1][(ni & 1) * 2 + 1] };
                    mma_bf16(acc[mi][ni], af[mi], bb);
                }
        }

        // ---- epilogue: y = 2*acc - sqn_j (unmasked) ----
        const int jc = ch * BN;
#pragma unroll
        for (int mi = 0; mi < 4; mi++) {
            int r0 = wm * 64 + mi * 16 + qrow, r1 = r0 + 8;
            size_t gY0 = (size_t)(cur_bm * 128 + r0) * NPAD + jc;
            size_t gY1 = (size_t)(cur_bm * 128 + r1) * NPAD + jc;
            const int s0 = mi * 2, s1 = mi * 2 + 1;
#pragma unroll
            for (int ni = 0; ni < 4; ni++) {
                int c = wn * 32 + ni * 8 + qcol * 2;
                float sq0 = s_sqnj[b][c], sq1 = s_sqnj[b][c + 1];
                float y00 = fmaf(2.f, acc[mi][ni][0], -sq0);
                float y01 = fmaf(2.f, acc[mi][ni][1], -sq1);
                float y10 = fmaf(2.f, acc[mi][ni][2], -sq0);
                float y11 = fmaf(2.f, acc[mi][ni][3], -sq1);
                *(__half2*)(g_Y + gY0 + c) = __floats2half2_rn(y00, y01);
                *(__half2*)(g_Y + gY1 + c) = __floats2half2_rn(y10, y11);
                if (jc + c < NODE) {
                    psum[s0] += y00 + y01;
                    psum2[s0] += y00 * y00 + y01 * y01;
                    pmax[s0] = fmaxf(pmax[s0], fmaxf(y00, y01));
                    psum[s1] += y10 + y11;
                    psum2[s1] += y10 * y10 + y11 * y11;
                    pmax[s1] = fmaxf(pmax[s1], fmaxf(y10, y11));
                }
            }
        }
        __syncthreads();
    }

    // final flush
#pragma unroll
    for (int s = 0; s < 8; s++) {
        float v = psum[s], v2 = psum2[s], m = pmax[s];
        v += __shfl_xor_sync(0xffffffffu, v, 1);
        v += __shfl_xor_sync(0xffffffffu, v, 2);
        v2 += __shfl_xor_sync(0xffffffffu, v2, 1);
        v2 += __shfl_xor_sync(0xffffffffu, v2, 2);
        m = fmaxf(m, __shfl_xor_sync(0xffffffffu, m, 1));
        m = fmaxf(m, __shfl_xor_sync(0xffffffffu, m, 2));
        if (qcol == 0) {
            int grow = cur_bm * 128 + wm * 64 + (s >> 1) * 16 + qrow + 8 * (s & 1);
            atomicAdd(&g_rsum[grow], v);
            atomicAdd(&g_rsum2[grow], v2);
            atomicMax(&g_rmaxU[grow], encf(m));
        }
    }
}

// ---------------- launch 4: logsumexp with analytic mask correction --------
__device__ float blockSum(float v) {
    __shared__ float scr[8];
    __shared__ float bc;
    v = warpSum(v);
    if ((threadIdx.x & 31) == 0) scr[threadIdx.x >> 5] = v;
    __syncthreads();
    if (threadIdx.x < 32) {
        float t = (threadIdx.x < 8) ? scr[threadIdx.x] : 0.f;
        t = warpSum(t);
        if (threadIdx.x == 0) bc = t;
    }
    __syncthreads();
    float r = bc;
    __syncthreads();
    return r;
}

__device__ __forceinline__ void unpack8(uint4 v, float* f) {
    float2 a = __half22float2(*(__half2*)&v.x);
    float2 b = __half22float2(*(__half2*)&v.y);
    float2 c = __half22float2(*(__half2*)&v.z);
    float2 d = __half22float2(*(__half2*)&v.w);
    f[0] = a.x; f[1] = a.y; f[2] = b.x; f[3] = b.y;
    f[4] = c.x; f[5] = c.y; f[6] = d.x; f[7] = d.y;
}

__global__ __launch_bounds__(256) void k_lse(const void* tp) {
    const int row = blockIdx.x;
    const int tid = threadIdx.x;
    const int pair = row >> 1, side = row & 1;
    const int is64 = g_tp64;
    const int l = readIdx(tp, 2LL * pair, is64);
    const int r = readIdx(tp, 2LL * pair + 1, is64);
    const float pos = g_pos[pair];
    const float sqa = g_sqn[side ? r : l];
    const float cm = pos - sqa + GAMMA_F;

    // analytic unmasked values at masked columns (exact identities):
    //   a==col -> y_old = sqa ;  partner col -> y_old = sqa - pos
    float yol, yor, ynl, ynr;
    float sum = g_rsum[row], sum2 = g_rsum2[row];
    if (l != r) {
        yol = side ? (sqa - pos) : sqa;
        yor = side ? sqa : (sqa - pos);
        ynl = -cm; ynr = -cm;
        sum += (ynl - yol) + (ynr - yor);
        sum2 += (ynl * ynl - yol * yol) + (ynr * ynr - yor * yor);
    } else {
        yol = sqa;
        ynl = -yol - 2.0f * cm;       // mask = -1 when l == r
        yor = 0.f; ynr = 0.f;
        sum += ynl - yol;
        sum2 += ynl * ynl - yol * yol;
    }
    const float mean = sum * (1.0f / 30000.0f);
    const float var = sum2 * (1.0f / 30000.0f) - mean * mean;
    const float a = LAMB_F / sqrtf(var);
    const float mx = decf(g_rmaxU[row]);

    const uint4* x4 = (const uint4*)(g_Y + (size_t)row * NPAD);
    float se = 0.f;
    for (int i = tid; i < 3750; i += 256) {   // 3750*8 = 30000
        float f[8];
        unpack8(x4[i], f);
#pragma unroll
        for (int c = 0; c < 8; c++) se += __expf(a * (f[c] - mx));
    }
    float setot = blockSum(se);
    if (tid == 0) {
        setot += __expf(a * (ynl - mx)) - __expf(a * (yol - mx));
        if (l != r) setot += __expf(a * (ynr - mx)) - __expf(a * (yor - mx));
        float lse = a * (mx - mean) + TAU_F + logf(setot);
        atomicAdd(&g_acc, (double)lse);
    }
}

__global__ void k_final(float* out) {
    if (threadIdx.x == 0 && blockIdx.x == 0)
        out[0] = (float)(g_acc / (double)NBATCH);
}

// ---------------- launch ----------------
extern "C" void kernel_launch(void* const* d_in, const int* in_sizes, int n_in,
                              void* d_out, int out_size) {
    const void* tp = nullptr;
    const void* adj = nullptr;
    const float* emb = nullptr;
    for (int i = 0; i < n_in; i++) {
        if (in_sizes[i] == NBATCH * 2)        tp  = d_in[i];
        else if (in_sizes[i] == 2 * NE)       adj = d_in[i];
        else if (in_sizes[i] == NODE * HID)   emb = (const float*)d_in[i];
    }
    float* out = (float*)d_out;

    k_zero<<<2048, 256>>>(tp, adj);                                        // idx 0
    k_scatter<<<(int)(((long long)NE * 32 + 255) / 256), 256>>>(adj, emb); // idx 1
    k_prep<<<NPAD / 8 + NBATCH / 8, 256>>>(tp);                            // idx 2

    // dynamic smem: A 32KB + 2 x B 32KB = 96KB per CTA (2 CTAs/SM)
    cudaFuncSetAttribute(k_mma, cudaFuncAttributeMaxDynamicSharedMemorySize, 98304);
    k_mma<<<GRID_MMA, 256, 98304>>>(tp);                                   // idx 3 (ncu)

    k_lse<<<AROWS, 256>>>(tp);                                             // idx 4
    k_final<<<1, 1>>>(out);                                                // idx 5
}

// round 10
// speedup vs baseline: 4.5263x; 1.0172x over previous
#include <cuda_runtime.h>
#include <cuda_fp16.h>
#include <cuda_bf16.h>
#include <math.h>
#include <stdint.h>

#define NODE   30000
#define NPAD   30080          // 235 * 128
#define HID    128
#define NE     600000
#define NBATCH 4096
#define AROWS  8192
#define BN     128
#define NCHUNK 235            // NPAD/BN
#define NBM    64             // AROWS/128
#define TOTW   (NBM * NCHUNK) // 15040
#define GRID_MMA 296          // 2 CTAs per SM
#define GAMMA_F 3.0f
#define LAMB_F  30.0f
#define TAU_F   10.0f

// ---------------- device globals ----------------
__device__ float  g_feat[(size_t)NPAD * HID];    // raw aggregated (unnormalized) fp32
__device__ __nv_bfloat16 g_featB[(size_t)NPAD * HID]; // normalized bf16 (7.7MB)
__device__ float  g_deg[NODE];
__device__ float  g_sqn[NPAD];
__device__ float  g_pos[NBATCH];
__device__ __half g_Y[(size_t)AROWS * NPAD];     // unmasked y = 2*dot - sqn_j, fp16
__device__ float  g_rsum[AROWS], g_rsum2[AROWS];
__device__ unsigned g_rmaxU[AROWS];
__device__ double g_acc;
__device__ int    g_tp64, g_adj64;

__device__ __forceinline__ int readIdx(const void* p, long long i, int is64) {
    if (is64) return (int)((const long long*)p)[i];
    return ((const int*)p)[i];
}
__device__ __forceinline__ uint32_t smem_u32(const void* p) {
    uint32_t a;
    asm("{ .reg .u64 t; cvta.to.shared.u64 t, %1; cvt.u32.u64 %0, t; }" : "=r"(a) : "l"(p));
    return a;
}
__device__ __forceinline__ void cp_async16(uint32_t s, const void* g) {
    asm volatile("cp.async.cg.shared.global [%0], [%1], 16;" :: "r"(s), "l"(g));
}
__device__ __forceinline__ void cp_commit() {
    asm volatile("cp.async.commit_group;" ::: "memory");
}
__device__ __forceinline__ void ldsm4(uint32_t* r, uint32_t addr) {
    asm volatile("ldmatrix.sync.aligned.m8n8.x4.shared.b16 {%0,%1,%2,%3}, [%4];"
        : "=r"(r[0]), "=r"(r[1]), "=r"(r[2]), "=r"(r[3]) : "r"(addr));
}
__device__ __forceinline__ void mma_bf16(float* d, const uint32_t* a, const uint32_t* b) {
    asm volatile(
        "mma.sync.aligned.m16n8k16.row.col.f32.bf16.bf16.f32 "
        "{%0,%1,%2,%3}, {%4,%5,%6,%7}, {%8,%9}, {%0,%1,%2,%3};"
        : "+f"(d[0]), "+f"(d[1]), "+f"(d[2]), "+f"(d[3])
        : "r"(a[0]), "r"(a[1]), "r"(a[2]), "r"(a[3]), "r"(b[0]), "r"(b[1]));
}
__device__ __forceinline__ unsigned encf(float f) {
    unsigned u = __float_as_uint(f);
    return (u & 0x80000000u) ? ~u : (u | 0x80000000u);
}
__device__ __forceinline__ float decf(unsigned e) {
    return (e & 0x80000000u) ? __uint_as_float(e & 0x7FFFFFFFu) : __uint_as_float(~e);
}

// ---------------- launch 0: zero + dtype detect ----------------
__global__ void k_zero(const void* tp, const void* adj) {
    size_t i = (size_t)blockIdx.x * blockDim.x + threadIdx.x;
    size_t stride = (size_t)gridDim.x * blockDim.x;
    float4 z = make_float4(0.f, 0.f, 0.f, 0.f);
    float4* f4 = (float4*)g_feat;
    size_t n4 = (size_t)NPAD * HID / 4;
    for (size_t j = i; j < n4; j += stride) f4[j] = z;
    for (size_t j = i; j < NODE; j += stride) g_deg[j] = 0.f;
    for (size_t j = i; j < AROWS; j += stride) {
        g_rsum[j] = 0.f; g_rsum2[j] = 0.f; g_rmaxU[j] = encf(-3.0e38f);
    }
    if (i == 0) {
        g_acc = 0.0;
        const int* a = (const int*)tp;
        int all0 = 1;
        for (int k = 0; k < 16; k++) if (a[2 * k + 1] != 0) all0 = 0;
        g_tp64 = all0;
        const int* b = (const int*)adj;
        all0 = 1;
        for (int k = 0; k < 16; k++) if (b[2 * k + 1] != 0) all0 = 0;
        g_adj64 = all0;
    }
}

// ---------------- launch 1: scatter raw emb + degree ----------------
__global__ void k_scatter(const void* adj, const float* emb) {
    long long idx = (long long)blockIdx.x * blockDim.x + threadIdx.x;
    if (idx >= (long long)NE * 32) return;
    int e = (int)(idx >> 5);
    int lane = (int)(idx & 31);
    int is64 = g_adj64;
    int r = readIdx(adj, e, is64);
    int c = readIdx(adj, (long long)NE + e, is64);
    if (lane == 0) atomicAdd(&g_deg[r], 1.0f);
    float4 v = ((const float4*)emb)[(size_t)c * 32 + lane];
    atomicAdd(((float4*)g_feat) + (size_t)r * 32 + lane, v);
}

__device__ __forceinline__ float warpSum(float v) {
    for (int o = 16; o; o >>= 1) v += __shfl_xor_sync(0xffffffffu, v, o);
    return v;
}

// ---------------- launch 2: normalize -> bf16, sqn, pos ----------------
__global__ __launch_bounds__(256) void k_prep(const void* tp) {
    const int tid = threadIdx.x, lane = tid & 31, w = tid >> 5;
    const int blk = blockIdx.x;
    if (blk < NPAD / 8) {
        int row = blk * 8 + w;
        float4 v = ((const float4*)g_feat)[(size_t)row * 32 + lane];
        float wgt = 1.0f;
        if (row < NODE) {
            float d = g_deg[row];
            wgt = (d > 0.f) ? (1.0f / d) : 1.0f;
        }
        float x0 = v.x * wgt, x1 = v.y * wgt, x2 = v.z * wgt, x3 = v.w * wgt;
        float s = x0 * x0 + x1 * x1 + x2 * x2 + x3 * x3;
        float stot = warpSum(s);
        if (lane == 0) g_sqn[row] = stot;
        __nv_bfloat162 p0 = __float22bfloat162_rn(make_float2(x0, x1));
        __nv_bfloat162 p1 = __float22bfloat162_rn(make_float2(x2, x3));
        uint2 u;
        u.x = *(uint32_t*)&p0;
        u.y = *(uint32_t*)&p1;
        ((uint2*)(g_featB + (size_t)row * HID))[lane] = u;
    } else {
        int pr = (blk - NPAD / 8) * 8 + w;
        int is64 = g_tp64;
        int l = readIdx(tp, 2LL * pr, is64);
        int r = readIdx(tp, 2LL * pr + 1, is64);
        float dl = g_deg[l], dr = g_deg[r];
        float wl = (dl > 0.f) ? (1.0f / dl) : 1.0f;
        float wr = (dr > 0.f) ? (1.0f / dr) : 1.0f;
        float4 a = ((const float4*)g_feat)[(size_t)l * 32 + lane];
        float4 b = ((const float4*)g_feat)[(size_t)r * 32 + lane];
        float dx = wl * a.x - wr * b.x, dy = wl * a.y - wr * b.y;
        float dz = wl * a.z - wr * b.z, dw = wl * a.w - wr * b.w;
        float s = warpSum(dx * dx + dy * dy + dz * dz + dw * dw);
        if (lane == 0) g_pos[pr] = s;
    }
}

// ---------------- launch 3: persistent bf16 GEMM, 2 CTAs/SM ping-pong -----
// 296 CTAs x 128 threads (4 warps, 2m x 2n, warp tile 64x64). Chunk = 128
// A-rows x 128 cols, K=128. Large warp tile cuts LDSM fragment traffic to
// 128KB/chunk (A re-read 2x, B re-read 2x). A persistent per bm; B double-
// buffered. Epilogue: y = 2*dot - sqn_j (mask applied analytically in k_lse).
__global__ __launch_bounds__(128, 2) void k_mma(const void* tp) {
    extern __shared__ char dsm[];
    char* pA = dsm;                                // 32KB
    char* pB[2] = { dsm + 32768, dsm + 65536 };    // 2 x 32KB
    __shared__ float s_sqnj[2][BN];

    const int tid = threadIdx.x;
    const int lane = tid & 31, warp = tid >> 5;
    const int wm = warp >> 1, wn = warp & 1;       // 2m x 2n
    const int qrow = lane >> 2, qcol = lane & 3;
    const int is64 = g_tp64;
    const uint32_t sAaddr = smem_u32(pA);
    const uint32_t sBaddr[2] = { smem_u32(pB[0]), smem_u32(pB[1]) };
    const uint32_t sqnjaddr = smem_u32(s_sqnj);

    // ldmatrix lane address components
    const int aRow0 = wm * 64 + (lane & 15);       // + mi*16
    const int aKh   = (lane >> 4) & 1;
    const int bRowL = (lane & 7) + (((lane >> 4) & 1) << 3);   // + wn*64 + nt*16
    const int bKh   = (lane >> 3) & 1;

    const long long t0 = ((long long)blockIdx.x * TOTW) / GRID_MMA;
    const long long t1 = ((long long)(blockIdx.x + 1) * TOTW) / GRID_MMA;
    if (t0 >= t1) return;

    int cur_bm = -1;
    float psum[8], psum2[8], pmax[8];
#pragma unroll
    for (int s = 0; s < 8; s++) { psum[s] = 0.f; psum2[s] = 0.f; pmax[s] = -3.0e38f; }

    // prefetch B + sqn for first work item
    {
        int nb = (int)(t0 % NCHUNK) * BN;
#pragma unroll
        for (int q = 0; q < 16; q++) {
            int idx = tid + q * 128;               // 0..2047
            int row = idx >> 4, cc = idx & 15;
            cp_async16(sBaddr[0] + row * 256 + ((cc ^ (row & 7)) << 4),
                       g_featB + (size_t)(nb + row) * HID + cc * 8);
        }
        if (tid < 32) cp_async16(sqnjaddr + tid * 16, &g_sqn[nb + tid * 4]);
        cp_commit();
    }

    for (long long t = t0; t < t1; t++) {
        const int b = (int)((t - t0) & 1);
        const int bm = (int)(t / NCHUNK);
        const int ch = (int)(t % NCHUNK);

        if (bm != cur_bm) {
            if (cur_bm >= 0) {   // flush stats of previous bm
#pragma unroll
                for (int s = 0; s < 8; s++) {
                    float v = psum[s], v2 = psum2[s], m = pmax[s];
                    v += __shfl_xor_sync(0xffffffffu, v, 1);
                    v += __shfl_xor_sync(0xffffffffu, v, 2);
                    v2 += __shfl_xor_sync(0xffffffffu, v2, 1);
                    v2 += __shfl_xor_sync(0xffffffffu, v2, 2);
                    m = fmaxf(m, __shfl_xor_sync(0xffffffffu, m, 1));
                    m = fmaxf(m, __shfl_xor_sync(0xffffffffu, m, 2));
                    if (qcol == 0) {
                        int grow = cur_bm * 128 + wm * 64 + (s >> 1) * 16 + qrow + 8 * (s & 1);
                        atomicAdd(&g_rsum[grow], v);
                        atomicAdd(&g_rsum2[grow], v2);
                        atomicMax(&g_rmaxU[grow], encf(m));
                    }
                    psum[s] = 0.f; psum2[s] = 0.f; pmax[s] = -3.0e38f;
                }
            }
            // A tile: 128 gathered rows, bf16, swizzled; 2048 chunks of 16B
#pragma unroll
            for (int q = 0; q < 16; q++) {
                int idx = tid + q * 128;
                int row = idx >> 4, cc = idx & 15;
                int g = bm * 128 + row;
                int pair = g >> 1, side = g & 1;
                int arow = readIdx(tp, 2LL * pair + side, is64);
                cp_async16(sAaddr + row * 256 + ((cc ^ (row & 7)) << 4),
                           g_featB + (size_t)arow * HID + cc * 8);
            }
            cp_commit();
            cur_bm = bm;
        }

        // prefetch next B
        if (t + 1 < t1) {
            int nb = (int)((t + 1) % NCHUNK) * BN;
            uint32_t dst = sBaddr[b ^ 1];
#pragma unroll
            for (int q = 0; q < 16; q++) {
                int idx = tid + q * 128;
                int row = idx >> 4, cc = idx & 15;
                cp_async16(dst + row * 256 + ((cc ^ (row & 7)) << 4),
                           g_featB + (size_t)(nb + row) * HID + cc * 8);
            }
            if (tid < 32) cp_async16(sqnjaddr + (b ^ 1) * (BN * 4) + tid * 16, &g_sqn[nb + tid * 4]);
            cp_commit();
            asm volatile("cp.async.wait_group 1;" ::: "memory");
        } else {
            asm volatile("cp.async.wait_group 0;" ::: "memory");
        }
        __syncthreads();

        // ---- compute 128x128 chunk: 8 kgroups x (8 LDSM.x4 + 32 HMMA) ----
        float acc[4][8][4];
#pragma unroll
        for (int mi = 0; mi < 4; mi++)
#pragma unroll
            for (int ni = 0; ni < 8; ni++)
#pragma unroll
                for (int c = 0; c < 4; c++) acc[mi][ni][c] = 0.f;

        const uint32_t sB = sBaddr[b];
#pragma unroll
        for (int kg = 0; kg < 8; kg++) {
            uint32_t af[4][4], bf[4][4];
            const int kcA = 2 * kg + aKh;
            const int kcB = 2 * kg + bKh;
#pragma unroll
            for (int mi = 0; mi < 4; mi++) {
                int row = aRow0 + mi * 16;
                ldsm4(af[mi], sAaddr + row * 256 + ((kcA ^ (row & 7)) << 4));
            }
#pragma unroll
            for (int nt = 0; nt < 4; nt++) {
                int row = wn * 64 + nt * 16 + bRowL;
                ldsm4(bf[nt], sB + row * 256 + ((kcB ^ (row & 7)) << 4));
            }
#pragma unroll
            for (int mi = 0; mi < 4; mi++)
#pragma unroll
                for (int ni = 0; ni < 8; ni++) {
                    uint32_t bb[2] = { bf[ni >> 1][(ni & 1) * 2], bf[ni >> 1][(ni & 1) * 2 + 1] };
                    mma_bf16(acc[mi][ni], af[mi], bb);
                }
        }

        // ---- epilogue: y = 2*acc - sqn_j (unmasked) ----
        const int jc = ch * BN;
#pragma unroll
        for (int mi = 0; mi < 4; mi++) {
            int r0 = wm * 64 + mi * 16 + qrow, r1 = r0 + 8;
            size_t gY0 = (size_t)(cur_bm * 128 + r0) * NPAD + jc;
            size_t gY1 = (size_t)(cur_bm * 128 + r1) * NPAD + jc;
            const int s0 = mi * 2, s1 = mi * 2 + 1;
#pragma unroll
            for (int ni = 0; ni < 8; ni++) {
                int c = wn * 64 + ni * 8 + qcol * 2;
                float sq0 = s_sqnj[b][c], sq1 = s_sqnj[b][c + 1];
                float y00 = fmaf(2.f, acc[mi][ni][0], -sq0);
                float y01 = fmaf(2.f, acc[mi][ni][1], -sq1);
                float y10 = fmaf(2.f, acc[mi][ni][2], -sq0);
                float y11 = fmaf(2.f, acc[mi][ni][3], -sq1);
                *(__half2*)(g_Y + gY0 + c) = __floats2half2_rn(y00, y01);
                *(__half2*)(g_Y + gY1 + c) = __floats2half2_rn(y10, y11);
                if (jc + c < NODE) {
                    psum[s0] += y00 + y01;
                    psum2[s0] += y00 * y00 + y01 * y01;
                    pmax[s0] = fmaxf(pmax[s0], fmaxf(y00, y01));
                    psum[s1] += y10 + y11;
                    psum2[s1] += y10 * y10 + y11 * y11;
                    pmax[s1] = fmaxf(pmax[s1], fmaxf(y10, y11));
                }
            }
        }
        __syncthreads();
    }

    // final flush
#pragma unroll
    for (int s = 0; s < 8; s++) {
        float v = psum[s], v2 = psum2[s], m = pmax[s];
        v += __shfl_xor_sync(0xffffffffu, v, 1);
        v += __shfl_xor_sync(0xffffffffu, v, 2);
        v2 += __shfl_xor_sync(0xffffffffu, v2, 1);
        v2 += __shfl_xor_sync(0xffffffffu, v2, 2);
        m = fmaxf(m, __shfl_xor_sync(0xffffffffu, m, 1));
        m = fmaxf(m, __shfl_xor_sync(0xffffffffu, m, 2));
        if (qcol == 0) {
            int grow = cur_bm * 128 + wm * 64 + (s >> 1) * 16 + qrow + 8 * (s & 1);
            atomicAdd(&g_rsum[grow], v);
            atomicAdd(&g_rsum2[grow], v2);
            atomicMax(&g_rmaxU[grow], encf(m));
        }
    }
}

// ---------------- launch 4: logsumexp with analytic mask correction --------
__device__ float blockSum(float v) {
    __shared__ float scr[8];
    __shared__ float bc;
    v = warpSum(v);
    if ((threadIdx.x & 31) == 0) scr[threadIdx.x >> 5] = v;
    __syncthreads();
    if (threadIdx.x < 32) {
        float t = (threadIdx.x < 8) ? scr[threadIdx.x] : 0.f;
        t = warpSum(t);
        if (threadIdx.x == 0) bc = t;
    }
    __syncthreads();
    float r = bc;
    __syncthreads();
    return r;
}

__device__ __forceinline__ void unpack8(uint4 v, float* f) {
    float2 a = __half22float2(*(__half2*)&v.x);
    float2 b = __half22float2(*(__half2*)&v.y);
    float2 c = __half22float2(*(__half2*)&v.z);
    float2 d = __half22float2(*(__half2*)&v.w);
    f[0] = a.x; f[1] = a.y; f[2] = b.x; f[3] = b.y;
    f[4] = c.x; f[5] = c.y; f[6] = d.x; f[7] = d.y;
}

__global__ __launch_bounds__(256) void k_lse(const void* tp) {
    const int row = blockIdx.x;
    const int tid = threadIdx.x;
    const int pair = row >> 1, side = row & 1;
    const int is64 = g_tp64;
    const int l = readIdx(tp, 2LL * pair, is64);
    const int r = readIdx(tp, 2LL * pair + 1, is64);
    const float pos = g_pos[pair];
    const float sqa = g_sqn[side ? r : l];
    const float cm = pos - sqa + GAMMA_F;

    // analytic unmasked values at masked columns (exact identities):
    //   a==col -> y_old = sqa ;  partner col -> y_old = sqa - pos
    float yol, yor, ynl, ynr;
    float sum = g_rsum[row], sum2 = g_rsum2[row];
    if (l != r) {
        yol = side ? (sqa - pos) : sqa;
        yor = side ? sqa : (sqa - pos);
        ynl = -cm; ynr = -cm;
        sum += (ynl - yol) + (ynr - yor);
        sum2 += (ynl * ynl - yol * yol) + (ynr * ynr - yor * yor);
    } else {
        yol = sqa;
        ynl = -yol - 2.0f * cm;       // mask = -1 when l == r
        yor = 0.f; ynr = 0.f;
        sum += ynl - yol;
        sum2 += ynl * ynl - yol * yol;
    }
    const float mean = sum * (1.0f / 30000.0f);
    const float var = sum2 * (1.0f / 30000.0f) - mean * mean;
    const float a = LAMB_F / sqrtf(var);
    const float mx = decf(g_rmaxU[row]);

    const uint4* x4 = (const uint4*)(g_Y + (size_t)row * NPAD);
    float se = 0.f;
    for (int i = tid; i < 3750; i += 256) {   // 3750*8 = 30000
        float f[8];
        unpack8(x4[i], f);
#pragma unroll
        for (int c = 0; c < 8; c++) se += __expf(a * (f[c] - mx));
    }
    float setot = blockSum(se);
    if (tid == 0) {
        setot += __expf(a * (ynl - mx)) - __expf(a * (yol - mx));
        if (l != r) setot += __expf(a * (ynr - mx)) - __expf(a * (yor - mx));
        float lse = a * (mx - mean) + TAU_F + logf(setot);
        atomicAdd(&g_acc, (double)lse);
    }
}

__global__ void k_final(float* out) {
    if (threadIdx.x == 0 && blockIdx.x == 0)
        out[0] = (float)(g_acc / (double)NBATCH);
}

// ---------------- launch ----------------
extern "C" void kernel_launch(void* const* d_in, const int* in_sizes, int n_in,
                              void* d_out, int out_size) {
    const void* tp = nullptr;
    const void* adj = nullptr;
    const float* emb = nullptr;
    for (int i = 0; i < n_in; i++) {
        if (in_sizes[i] == NBATCH * 2)        tp  = d_in[i];
        else if (in_sizes[i] == 2 * NE)       adj = d_in[i];
        else if (in_sizes[i] == NODE * HID)   emb = (const float*)d_in[i];
    }
    float* out = (float*)d_out;

    k_zero<<<2048, 256>>>(tp, adj);                                        // idx 0
    k_scatter<<<(int)(((long long)NE * 32 + 255) / 256), 256>>>(adj, emb); // idx 1
    k_prep<<<NPAD / 8 + NBATCH / 8, 256>>>(tp);                            // idx 2

    // dynamic smem: A 32KB + 2 x B 32KB = 96KB per CTA (2 CTAs/SM)
    cudaFuncSetAttribute(k_mma, cudaFuncAttributeMaxDynamicSharedMemorySize, 98304);
    k_mma<<<GRID_MMA, 128, 98304>>>(tp);                                   // idx 3 (ncu)

    k_lse<<<AROWS, 256>>>(tp);                                             // idx 4
    k_final<<<1, 1>>>(out);                                                // idx 5
}

// round 11
// speedup vs baseline: 4.8457x; 1.0706x over previous
#include <cuda_runtime.h>
#include <cuda_fp16.h>
#include <cuda_bf16.h>
#include <math.h>
#include <stdint.h>

#define NODE   30000
#define NPAD   30080          // 235 * 128
#define HID    128
#define NE     600000
#define NBATCH 4096
#define AROWS  8192
#define BN     128
#define NCHUNK 235            // NPAD/BN
#define NBM    64             // AROWS/128
#define TOTW   (NBM * NCHUNK) // 15040
#define GRID_MMA 296          // 2 CTAs per SM
#define GAMMA_F 3.0f
#define LAMB_F  30.0f
#define TAU_F   10.0f

// ---------------- device globals ----------------
__device__ float  g_feat[(size_t)NPAD * HID];    // raw aggregated (unnormalized) fp32
__device__ __nv_bfloat16 g_featB[(size_t)NPAD * HID]; // normalized bf16 (7.7MB)
__device__ float  g_deg[NODE];
__device__ float  g_sqn[NPAD];
__device__ float  g_pos[NBATCH];
__device__ __half g_Y[(size_t)AROWS * NPAD];     // unmasked y = 2*dot - sqn_j, fp16
__device__ float  g_rsum[AROWS], g_rsum2[AROWS];
__device__ unsigned g_rmaxU[AROWS];
__device__ double g_acc;
__device__ int    g_tp64, g_adj64;

__device__ __forceinline__ int readIdx(const void* p, long long i, int is64) {
    if (is64) return (int)((const long long*)p)[i];
    return ((const int*)p)[i];
}
__device__ __forceinline__ uint32_t smem_u32(const void* p) {
    uint32_t a;
    asm("{ .reg .u64 t; cvta.to.shared.u64 t, %1; cvt.u32.u64 %0, t; }" : "=r"(a) : "l"(p));
    return a;
}
__device__ __forceinline__ void cp_async16(uint32_t s, const void* g) {
    asm volatile("cp.async.cg.shared.global [%0], [%1], 16;" :: "r"(s), "l"(g));
}
__device__ __forceinline__ void cp_commit() {
    asm volatile("cp.async.commit_group;" ::: "memory");
}
__device__ __forceinline__ void ldsm4(uint32_t* r, uint32_t addr) {
    asm volatile("ldmatrix.sync.aligned.m8n8.x4.shared.b16 {%0,%1,%2,%3}, [%4];"
        : "=r"(r[0]), "=r"(r[1]), "=r"(r[2]), "=r"(r[3]) : "r"(addr));
}
__device__ __forceinline__ void stsm4(uint32_t addr, const uint32_t* r) {
    asm volatile("stmatrix.sync.aligned.m8n8.x4.shared.b16 [%0], {%1,%2,%3,%4};"
        :: "r"(addr), "r"(r[0]), "r"(r[1]), "r"(r[2]), "r"(r[3]) : "memory");
}
__device__ __forceinline__ void mma_bf16(float* d, const uint32_t* a, const uint32_t* b) {
    asm volatile(
        "mma.sync.aligned.m16n8k16.row.col.f32.bf16.bf16.f32 "
        "{%0,%1,%2,%3}, {%4,%5,%6,%7}, {%8,%9}, {%0,%1,%2,%3};"
        : "+f"(d[0]), "+f"(d[1]), "+f"(d[2]), "+f"(d[3])
        : "r"(a[0]), "r"(a[1]), "r"(a[2]), "r"(a[3]), "r"(b[0]), "r"(b[1]));
}
__device__ __forceinline__ unsigned encf(float f) {
    unsigned u = __float_as_uint(f);
    return (u & 0x80000000u) ? ~u : (u | 0x80000000u);
}
__device__ __forceinline__ float decf(unsigned e) {
    return (e & 0x80000000u) ? __uint_as_float(e & 0x7FFFFFFFu) : __uint_as_float(~e);
}

// ---------------- launch 0: zero + dtype detect ----------------
__global__ void k_zero(const void* tp, const void* adj) {
    size_t i = (size_t)blockIdx.x * blockDim.x + threadIdx.x;
    size_t stride = (size_t)gridDim.x * blockDim.x;
    float4 z = make_float4(0.f, 0.f, 0.f, 0.f);
    float4* f4 = (float4*)g_feat;
    size_t n4 = (size_t)NPAD * HID / 4;
    for (size_t j = i; j < n4; j += stride) f4[j] = z;
    for (size_t j = i; j < NODE; j += stride) g_deg[j] = 0.f;
    for (size_t j = i; j < AROWS; j += stride) {
        g_rsum[j] = 0.f; g_rsum2[j] = 0.f; g_rmaxU[j] = encf(-3.0e38f);
    }
    if (i == 0) {
        g_acc = 0.0;
        const int* a = (const int*)tp;
        int all0 = 1;
        for (int k = 0; k < 16; k++) if (a[2 * k + 1] != 0) all0 = 0;
        g_tp64 = all0;
        const int* b = (const int*)adj;
        all0 = 1;
        for (int k = 0; k < 16; k++) if (b[2 * k + 1] != 0) all0 = 0;
        g_adj64 = all0;
    }
}

// ---------------- launch 1: scatter raw emb + degree ----------------
__global__ void k_scatter(const void* adj, const float* emb) {
    long long idx = (long long)blockIdx.x * blockDim.x + threadIdx.x;
    if (idx >= (long long)NE * 32) return;
    int e = (int)(idx >> 5);
    int lane = (int)(idx & 31);
    int is64 = g_adj64;
    int r = readIdx(adj, e, is64);
    int c = readIdx(adj, (long long)NE + e, is64);
    if (lane == 0) atomicAdd(&g_deg[r], 1.0f);
    float4 v = ((const float4*)emb)[(size_t)c * 32 + lane];
    atomicAdd(((float4*)g_feat) + (size_t)r * 32 + lane, v);
}

__device__ __forceinline__ float warpSum(float v) {
    for (int o = 16; o; o >>= 1) v += __shfl_xor_sync(0xffffffffu, v, o);
    return v;
}

// ---------------- launch 2: normalize -> bf16, sqn, pos ----------------
__global__ __launch_bounds__(256) void k_prep(const void* tp) {
    const int tid = threadIdx.x, lane = tid & 31, w = tid >> 5;
    const int blk = blockIdx.x;
    if (blk < NPAD / 8) {
        int row = blk * 8 + w;
        float4 v = ((const float4*)g_feat)[(size_t)row * 32 + lane];
        float wgt = 1.0f;
        if (row < NODE) {
            float d = g_deg[row];
            wgt = (d > 0.f) ? (1.0f / d) : 1.0f;
        }
        float x0 = v.x * wgt, x1 = v.y * wgt, x2 = v.z * wgt, x3 = v.w * wgt;
        float s = x0 * x0 + x1 * x1 + x2 * x2 + x3 * x3;
        float stot = warpSum(s);
        if (lane == 0) g_sqn[row] = stot;
        __nv_bfloat162 p0 = __float22bfloat162_rn(make_float2(x0, x1));
        __nv_bfloat162 p1 = __float22bfloat162_rn(make_float2(x2, x3));
        uint2 u;
        u.x = *(uint32_t*)&p0;
        u.y = *(uint32_t*)&p1;
        ((uint2*)(g_featB + (size_t)row * HID))[lane] = u;
    } else {
        int pr = (blk - NPAD / 8) * 8 + w;
        int is64 = g_tp64;
        int l = readIdx(tp, 2LL * pr, is64);
        int r = readIdx(tp, 2LL * pr + 1, is64);
        float dl = g_deg[l], dr = g_deg[r];
        float wl = (dl > 0.f) ? (1.0f / dl) : 1.0f;
        float wr = (dr > 0.f) ? (1.0f / dr) : 1.0f;
        float4 a = ((const float4*)g_feat)[(size_t)l * 32 + lane];
        float4 b = ((const float4*)g_feat)[(size_t)r * 32 + lane];
        float dx = wl * a.x - wr * b.x, dy = wl * a.y - wr * b.y;
        float dz = wl * a.z - wr * b.z, dw = wl * a.w - wr * b.w;
        float s = warpSum(dx * dx + dy * dy + dz * dz + dw * dw);
        if (lane == 0) g_pos[pr] = s;
    }
}

// ---------------- launch 3: persistent bf16 GEMM, 2 CTAs/SM ping-pong -----
// 296 CTAs x 128 threads (4 warps, 2m x 2n, warp tile 64x64). Chunk = 128
// A-rows x 128 cols, K=128. Epilogue: y = 2*dot - sqn_j packed to half2 and
// STAGED through the just-consumed B buffer via stmatrix (swizzled,
// conflict-free), then streamed to g_Y with coalesced LDS.128 + STG.128 —
// cuts Y-store L1 wavefronts ~2.7x vs scattered half2 STG.
__global__ __launch_bounds__(128, 2) void k_mma(const void* tp) {
    extern __shared__ char dsm[];
    char* pA = dsm;                                // 32KB
    char* pB[2] = { dsm + 32768, dsm + 65536 };    // 2 x 32KB
    __shared__ float s_sqnj[2][BN];

    const int tid = threadIdx.x;
    const int lane = tid & 31, warp = tid >> 5;
    const int wm = warp >> 1, wn = warp & 1;       // 2m x 2n
    const int qrow = lane >> 2, qcol = lane & 3;
    const int is64 = g_tp64;
    const uint32_t sAaddr = smem_u32(pA);
    const uint32_t sBaddr[2] = { smem_u32(pB[0]), smem_u32(pB[1]) };
    const uint32_t sqnjaddr = smem_u32(s_sqnj);

    // ldmatrix lane address components
    const int aRow0 = wm * 64 + (lane & 15);       // + mi*16
    const int aKh   = (lane >> 4) & 1;
    const int bRowL = (lane & 7) + (((lane >> 4) & 1) << 3);   // + wn*64 + nt*16
    const int bKh   = (lane >> 3) & 1;

    // stmatrix lane address components: tile t = lane>>3, row-in-tile l = lane&7
    const int stT = lane >> 3, stL = lane & 7;
    const int stRowBase = wm * 64 + ((stT & 1) << 3) + stL;    // + mi*16
    const int stCcBase  = wn * 8 + (stT >> 1);                 // + np*2 ; swizzle ^ stL

    const long long t0 = ((long long)blockIdx.x * TOTW) / GRID_MMA;
    const long long t1 = ((long long)(blockIdx.x + 1) * TOTW) / GRID_MMA;
    if (t0 >= t1) return;

    int cur_bm = -1;
    float psum[8], psum2[8], pmax[8];
#pragma unroll
    for (int s = 0; s < 8; s++) { psum[s] = 0.f; psum2[s] = 0.f; pmax[s] = -3.0e38f; }

    // prefetch B + sqn for first work item
    {
        int nb = (int)(t0 % NCHUNK) * BN;
#pragma unroll
        for (int q = 0; q < 16; q++) {
            int idx = tid + q * 128;               // 0..2047
            int row = idx >> 4, cc = idx & 15;
            cp_async16(sBaddr[0] + row * 256 + ((cc ^ (row & 7)) << 4),
                       g_featB + (size_t)(nb + row) * HID + cc * 8);
        }
        if (tid < 32) cp_async16(sqnjaddr + tid * 16, &g_sqn[nb + tid * 4]);
        cp_commit();
    }

    for (long long t = t0; t < t1; t++) {
        const int b = (int)((t - t0) & 1);
        const int bm = (int)(t / NCHUNK);
        const int ch = (int)(t % NCHUNK);

        if (bm != cur_bm) {
            if (cur_bm >= 0) {   // flush stats of previous bm
#pragma unroll
                for (int s = 0; s < 8; s++) {
                    float v = psum[s], v2 = psum2[s], m = pmax[s];
                    v += __shfl_xor_sync(0xffffffffu, v, 1);
                    v += __shfl_xor_sync(0xffffffffu, v, 2);
                    v2 += __shfl_xor_sync(0xffffffffu, v2, 1);
                    v2 += __shfl_xor_sync(0xffffffffu, v2, 2);
                    m = fmaxf(m, __shfl_xor_sync(0xffffffffu, m, 1));
                    m = fmaxf(m, __shfl_xor_sync(0xffffffffu, m, 2));
                    if (qcol == 0) {
                        int grow = cur_bm * 128 + wm * 64 + (s >> 1) * 16 + qrow + 8 * (s & 1);
                        atomicAdd(&g_rsum[grow], v);
                        atomicAdd(&g_rsum2[grow], v2);
                        atomicMax(&g_rmaxU[grow], encf(m));
                    }
                    psum[s] = 0.f; psum2[s] = 0.f; pmax[s] = -3.0e38f;
                }
            }
            // A tile: 128 gathered rows, bf16, swizzled; 2048 chunks of 16B
#pragma unroll
            for (int q = 0; q < 16; q++) {
                int idx = tid + q * 128;
                int row = idx >> 4, cc = idx & 15;
                int g = bm * 128 + row;
                int pair = g >> 1, side = g & 1;
                int arow = readIdx(tp, 2LL * pair + side, is64);
                cp_async16(sAaddr + row * 256 + ((cc ^ (row & 7)) << 4),
                           g_featB + (size_t)arow * HID + cc * 8);
            }
            cp_commit();
            cur_bm = bm;
        }

        // prefetch next B (into pB[b^1]; no overlap with current tile/staging)
        if (t + 1 < t1) {
            int nb = (int)((t + 1) % NCHUNK) * BN;
            uint32_t dst = sBaddr[b ^ 1];
#pragma unroll
            for (int q = 0; q < 16; q++) {
                int idx = tid + q * 128;
                int row = idx >> 4, cc = idx & 15;
                cp_async16(dst + row * 256 + ((cc ^ (row & 7)) << 4),
                           g_featB + (size_t)(nb + row) * HID + cc * 8);
            }
            if (tid < 32) cp_async16(sqnjaddr + (b ^ 1) * (BN * 4) + tid * 16, &g_sqn[nb + tid * 4]);
            cp_commit();
            asm volatile("cp.async.wait_group 1;" ::: "memory");
        } else {
            asm volatile("cp.async.wait_group 0;" ::: "memory");
        }
        __syncthreads();                           // (1) tile b ready

        // ---- compute 128x128 chunk: 8 kgroups x (8 LDSM.x4 + 32 HMMA) ----
        float acc[4][8][4];
#pragma unroll
        for (int mi = 0; mi < 4; mi++)
#pragma unroll
            for (int ni = 0; ni < 8; ni++)
#pragma unroll
                for (int c = 0; c < 4; c++) acc[mi][ni][c] = 0.f;

        const uint32_t sB = sBaddr[b];
#pragma unroll
        for (int kg = 0; kg < 8; kg++) {
            uint32_t af[4][4], bf[4][4];
            const int kcA = 2 * kg + aKh;
            const int kcB = 2 * kg + bKh;
#pragma unroll
            for (int mi = 0; mi < 4; mi++) {
                int row = aRow0 + mi * 16;
                ldsm4(af[mi], sAaddr + row * 256 + ((kcA ^ (row & 7)) << 4));
            }
#pragma unroll
            for (int nt = 0; nt < 4; nt++) {
                int row = wn * 64 + nt * 16 + bRowL;
                ldsm4(bf[nt], sB + row * 256 + ((kcB ^ (row & 7)) << 4));
            }
#pragma unroll
            for (int mi = 0; mi < 4; mi++)
#pragma unroll
                for (int ni = 0; ni < 8; ni++) {
                    uint32_t bb[2] = { bf[ni >> 1][(ni & 1) * 2], bf[ni >> 1][(ni & 1) * 2 + 1] };
                    mma_bf16(acc[mi][ni], af[mi], bb);
                }
        }

        __syncthreads();                           // (2) pB[b] fully consumed

        // ---- epilogue: y = 2*acc - sqn_j; stats; stmatrix-stage into pB[b] ----
        const int jc = ch * BN;
#pragma unroll
        for (int mi = 0; mi < 4; mi++) {
            const int s0 = mi * 2, s1 = s0 + 1;
#pragma unroll
            for (int np = 0; np < 4; np++) {
                uint32_t hh[4];
#pragma unroll
                for (int d = 0; d < 2; d++) {
                    int ni = np * 2 + d;
                    int c = wn * 64 + ni * 8 + qcol * 2;
                    float sq0 = s_sqnj[b][c], sq1 = s_sqnj[b][c + 1];
                    float y00 = fmaf(2.f, acc[mi][ni][0], -sq0);
                    float y01 = fmaf(2.f, acc[mi][ni][1], -sq1);
                    float y10 = fmaf(2.f, acc[mi][ni][2], -sq0);
                    float y11 = fmaf(2.f, acc[mi][ni][3], -sq1);
                    __half2 a0 = __floats2half2_rn(y00, y01);
                    __half2 a1 = __floats2half2_rn(y10, y11);
                    hh[d * 2 + 0] = *(uint32_t*)&a0;
                    hh[d * 2 + 1] = *(uint32_t*)&a1;
                    if (jc + c < NODE) {
                        psum[s0] += y00 + y01;
                        psum2[s0] += y00 * y00 + y01 * y01;
                        pmax[s0] = fmaxf(pmax[s0], fmaxf(y00, y01));
                        psum[s1] += y10 + y11;
                        psum2[s1] += y10 * y10 + y11 * y11;
                        pmax[s1] = fmaxf(pmax[s1], fmaxf(y10, y11));
                    }
                }
                // stmatrix x4: tiles {rows0-7,colsL}, {rows8-15,colsL}, {rows0-7,colsH}, {rows8-15,colsH}
                int rr = stRowBase + mi * 16;
                int cc = stCcBase + np * 2;
                stsm4(sB + rr * 256 + ((cc ^ stL) << 4), hh);
            }
        }

        __syncthreads();                           // (3) staging complete

        // ---- coalesced copy-out: 16 x (LDS.128 + STG.128) per thread ----
#pragma unroll
        for (int q = 0; q < 16; q++) {
            int idx = tid + q * 128;
            int row = idx >> 4, cc = idx & 15;
            uint4 v;
            uint32_t a = sB + row * 256 + ((cc ^ (row & 7)) << 4);
            asm volatile("ld.shared.v4.u32 {%0,%1,%2,%3}, [%4];"
                : "=r"(v.x), "=r"(v.y), "=r"(v.z), "=r"(v.w) : "r"(a));
            *(uint4*)(g_Y + (size_t)(cur_bm * 128 + row) * NPAD + jc + cc * 8) = v;
        }

        __syncthreads();                           // (4) copy reads done before next prefetch reuses pB[b]
    }

    // final flush
#pragma unroll
    for (int s = 0; s < 8; s++) {
        float v = psum[s], v2 = psum2[s], m = pmax[s];
        v += __shfl_xor_sync(0xffffffffu, v, 1);
        v += __shfl_xor_sync(0xffffffffu, v, 2);
        v2 += __shfl_xor_sync(0xffffffffu, v2, 1);
        v2 += __shfl_xor_sync(0xffffffffu, v2, 2);
        m = fmaxf(m, __shfl_xor_sync(0xffffffffu, m, 1));
        m = fmaxf(m, __shfl_xor_sync(0xffffffffu, m, 2));
        if (qcol == 0) {
            int grow = cur_bm * 128 + wm * 64 + (s >> 1) * 16 + qrow + 8 * (s & 1);
            atomicAdd(&g_rsum[grow], v);
            atomicAdd(&g_rsum2[grow], v2);
            atomicMax(&g_rmaxU[grow], encf(m));
        }
    }
}

// ---------------- launch 4: logsumexp with analytic mask correction --------
__device__ float blockSum(float v) {
    __shared__ float scr[8];
    __shared__ float bc;
    v = warpSum(v);
    if ((threadIdx.x & 31) == 0) scr[threadIdx.x >> 5] = v;
    __syncthreads();
    if (threadIdx.x < 32) {
        float t = (threadIdx.x < 8) ? scr[threadIdx.x] : 0.f;
        t = warpSum(t);
        if (threadIdx.x == 0) bc = t;
    }
    __syncthreads();
    float r = bc;
    __syncthreads();
    return r;
}

__device__ __forceinline__ void unpack8(uint4 v, float* f) {
    float2 a = __half22float2(*(__half2*)&v.x);
    float2 b = __half22float2(*(__half2*)&v.y);
    float2 c = __half22float2(*(__half2*)&v.z);
    float2 d = __half22float2(*(__half2*)&v.w);
    f[0] = a.x; f[1] = a.y; f[2] = b.x; f[3] = b.y;
    f[4] = c.x; f[5] = c.y; f[6] = d.x; f[7] = d.y;
}

__global__ __launch_bounds__(256) void k_lse(const void* tp) {
    const int row = blockIdx.x;
    const int tid = threadIdx.x;
    const int pair = row >> 1, side = row & 1;
    const int is64 = g_tp64;
    const int l = readIdx(tp, 2LL * pair, is64);
    const int r = readIdx(tp, 2LL * pair + 1, is64);
    const float pos = g_pos[pair];
    const float sqa = g_sqn[side ? r : l];
    const float cm = pos - sqa + GAMMA_F;

    // analytic unmasked values at masked columns (exact identities):
    //   a==col -> y_old = sqa ;  partner col -> y_old = sqa - pos
    float yol, yor, ynl, ynr;
    float sum = g_rsum[row], sum2 = g_rsum2[row];
    if (l != r) {
        yol = side ? (sqa - pos) : sqa;
        yor = side ? sqa : (sqa - pos);
        ynl = -cm; ynr = -cm;
        sum += (ynl - yol) + (ynr - yor);
        sum2 += (ynl * ynl - yol * yol) + (ynr * ynr - yor * yor);
    } else {
        yol = sqa;
        ynl = -yol - 2.0f * cm;       // mask = -1 when l == r
        yor = 0.f; ynr = 0.f;
        sum += ynl - yol;
        sum2 += ynl * ynl - yol * yol;
    }
    const float mean = sum * (1.0f / 30000.0f);
    const float var = sum2 * (1.0f / 30000.0f) - mean * mean;
    const float a = LAMB_F / sqrtf(var);
    const float mx = decf(g_rmaxU[row]);

    const uint4* x4 = (const uint4*)(g_Y + (size_t)row * NPAD);
    float se = 0.f;
    for (int i = tid; i < 3750; i += 256) {   // 3750*8 = 30000
        float f[8];
        unpack8(x4[i], f);
#pragma unroll
        for (int c = 0; c < 8; c++) se += __expf(a * (f[c] - mx));
    }
    float setot = blockSum(se);
    if (tid == 0) {
        setot += __expf(a * (ynl - mx)) - __expf(a * (yol - mx));
        if (l != r) setot += __expf(a * (ynr - mx)) - __expf(a * (yor - mx));
        float lse = a * (mx - mean) + TAU_F + logf(setot);
        atomicAdd(&g_acc, (double)lse);
    }
}

__global__ void k_final(float* out) {
    if (threadIdx.x == 0 && blockIdx.x == 0)
        out[0] = (float)(g_acc / (double)NBATCH);
}

// ---------------- launch ----------------
extern "C" void kernel_launch(void* const* d_in, const int* in_sizes, int n_in,
                              void* d_out, int out_size) {
    const void* tp = nullptr;
    const void* adj = nullptr;
    const float* emb = nullptr;
    for (int i = 0; i < n_in; i++) {
        if (in_sizes[i] == NBATCH * 2)        tp  = d_in[i];
        else if (in_sizes[i] == 2 * NE)       adj = d_in[i];
        else if (in_sizes[i] == NODE * HID)   emb = (const float*)d_in[i];
    }
    float* out = (float*)d_out;

    k_zero<<<2048, 256>>>(tp, adj);                                        // idx 0
    k_scatter<<<(int)(((long long)NE * 32 + 255) / 256), 256>>>(adj, emb); // idx 1
    k_prep<<<NPAD / 8 + NBATCH / 8, 256>>>(tp);                            // idx 2

    // dynamic smem: A 32KB + 2 x B 32KB = 96KB per CTA (2 CTAs/SM)
    cudaFuncSetAttribute(k_mma, cudaFuncAttributeMaxDynamicSharedMemorySize, 98304);
    k_mma<<<GRID_MMA, 128, 98304>>>(tp);                                   // idx 3 (ncu)

    k_lse<<<AROWS, 256>>>(tp);                                             // idx 4
    k_final<<<1, 1>>>(out);                                                // idx 5
}

// round 12
// speedup vs baseline: 4.9357x; 1.0186x over previous
#include <cuda_runtime.h>
#include <cuda_fp16.h>
#include <math.h>
#include <stdint.h>

#define NODE   30000
#define NPAD   30080          // 235 * 128
#define HID    128
#define NE     600000
#define NBATCH 4096
#define AROWS  8192
#define BN     128
#define NCHUNK 235            // NPAD/BN
#define NBM    64             // AROWS/128
#define TOTW   (NBM * NCHUNK) // 15040
#define GRID_MMA 296          // 2 CTAs per SM
#define GAMMA_F 3.0f
#define LAMB_F  30.0f
#define TAU_F   10.0f

// ---------------- device globals ----------------
__device__ float  g_feat[(size_t)NPAD * HID];    // raw aggregated (unnormalized) fp32
__device__ __half g_featH[(size_t)NPAD * HID];   // normalized fp16 (7.7MB)
__device__ float  g_deg[NODE];
__device__ float  g_sqn[NPAD];
__device__ float  g_pos[NBATCH];
__device__ __half g_Y[(size_t)AROWS * NPAD];     // unmasked y = 2*dot - sqn_j, fp16
__device__ float  g_rsum[AROWS], g_rsum2[AROWS];
__device__ unsigned g_rmaxU[AROWS];
__device__ double g_acc;
__device__ int    g_tp64, g_adj64;

__device__ __forceinline__ int readIdx(const void* p, long long i, int is64) {
    if (is64) return (int)((const long long*)p)[i];
    return ((const int*)p)[i];
}
__device__ __forceinline__ uint32_t smem_u32(const void* p) {
    uint32_t a;
    asm("{ .reg .u64 t; cvta.to.shared.u64 t, %1; cvt.u32.u64 %0, t; }" : "=r"(a) : "l"(p));
    return a;
}
__device__ __forceinline__ void cp_async16(uint32_t s, const void* g) {
    asm volatile("cp.async.cg.shared.global [%0], [%1], 16;" :: "r"(s), "l"(g));
}
__device__ __forceinline__ void cp_commit() {
    asm volatile("cp.async.commit_group;" ::: "memory");
}
__device__ __forceinline__ void ldsm4(uint32_t* r, uint32_t addr) {
    asm volatile("ldmatrix.sync.aligned.m8n8.x4.shared.b16 {%0,%1,%2,%3}, [%4];"
        : "=r"(r[0]), "=r"(r[1]), "=r"(r[2]), "=r"(r[3]) : "r"(addr));
}
__device__ __forceinline__ void stsm4(uint32_t addr, const uint32_t* r) {
    asm volatile("stmatrix.sync.aligned.m8n8.x4.shared.b16 [%0], {%1,%2,%3,%4};"
        :: "r"(addr), "r"(r[0]), "r"(r[1]), "r"(r[2]), "r"(r[3]) : "memory");
}
// f16 x f16 -> f16 accumulate (2x rate vs f32 acc; D/C = 2 regs = 4 halves)
__device__ __forceinline__ void mma_f16(uint32_t* d, const uint32_t* a, const uint32_t* b) {
    asm volatile(
        "mma.sync.aligned.m16n8k16.row.col.f16.f16.f16.f16 "
        "{%0,%1}, {%2,%3,%4,%5}, {%6,%7}, {%0,%1};"
        : "+r"(d[0]), "+r"(d[1])
        : "r"(a[0]), "r"(a[1]), "r"(a[2]), "r"(a[3]), "r"(b[0]), "r"(b[1]));
}
__device__ __forceinline__ unsigned encf(float f) {
    unsigned u = __float_as_uint(f);
    return (u & 0x80000000u) ? ~u : (u | 0x80000000u);
}
__device__ __forceinline__ float decf(unsigned e) {
    return (e & 0x80000000u) ? __uint_as_float(e & 0x7FFFFFFFu) : __uint_as_float(~e);
}

// ---------------- launch 0: zero + dtype detect ----------------
__global__ void k_zero(const void* tp, const void* adj) {
    size_t i = (size_t)blockIdx.x * blockDim.x + threadIdx.x;
    size_t stride = (size_t)gridDim.x * blockDim.x;
    float4 z = make_float4(0.f, 0.f, 0.f, 0.f);
    float4* f4 = (float4*)g_feat;
    size_t n4 = (size_t)NPAD * HID / 4;
    for (size_t j = i; j < n4; j += stride) f4[j] = z;
    for (size_t j = i; j < NODE; j += stride) g_deg[j] = 0.f;
    for (size_t j = i; j < AROWS; j += stride) {
        g_rsum[j] = 0.f; g_rsum2[j] = 0.f; g_rmaxU[j] = encf(-3.0e38f);
    }
    if (i == 0) {
        g_acc = 0.0;
        const int* a = (const int*)tp;
        int all0 = 1;
        for (int k = 0; k < 16; k++) if (a[2 * k + 1] != 0) all0 = 0;
        g_tp64 = all0;
        const int* b = (const int*)adj;
        all0 = 1;
        for (int k = 0; k < 16; k++) if (b[2 * k + 1] != 0) all0 = 0;
        g_adj64 = all0;
    }
}

// ---------------- launch 1: scatter raw emb + degree ----------------
__global__ void k_scatter(const void* adj, const float* emb) {
    long long idx = (long long)blockIdx.x * blockDim.x + threadIdx.x;
    if (idx >= (long long)NE * 32) return;
    int e = (int)(idx >> 5);
    int lane = (int)(idx & 31);
    int is64 = g_adj64;
    int r = readIdx(adj, e, is64);
    int c = readIdx(adj, (long long)NE + e, is64);
    if (lane == 0) atomicAdd(&g_deg[r], 1.0f);
    float4 v = ((const float4*)emb)[(size_t)c * 32 + lane];
    atomicAdd(((float4*)g_feat) + (size_t)r * 32 + lane, v);
}

__device__ __forceinline__ float warpSum(float v) {
    for (int o = 16; o; o >>= 1) v += __shfl_xor_sync(0xffffffffu, v, o);
    return v;
}

// ---------------- launch 2: normalize -> fp16, sqn, pos ----------------
__global__ __launch_bounds__(256) void k_prep(const void* tp) {
    const int tid = threadIdx.x, lane = tid & 31, w = tid >> 5;
    const int blk = blockIdx.x;
    if (blk < NPAD / 8) {
        int row = blk * 8 + w;
        float4 v = ((const float4*)g_feat)[(size_t)row * 32 + lane];
        float wgt = 1.0f;
        if (row < NODE) {
            float d = g_deg[row];
            wgt = (d > 0.f) ? (1.0f / d) : 1.0f;
        }
        float x0 = v.x * wgt, x1 = v.y * wgt, x2 = v.z * wgt, x3 = v.w * wgt;
        float s = x0 * x0 + x1 * x1 + x2 * x2 + x3 * x3;
        float stot = warpSum(s);
        if (lane == 0) g_sqn[row] = stot;
        __half2 p0 = __floats2half2_rn(x0, x1);
        __half2 p1 = __floats2half2_rn(x2, x3);
        uint2 u;
        u.x = *(uint32_t*)&p0;
        u.y = *(uint32_t*)&p1;
        ((uint2*)(g_featH + (size_t)row * HID))[lane] = u;
    } else {
        int pr = (blk - NPAD / 8) * 8 + w;
        int is64 = g_tp64;
        int l = readIdx(tp, 2LL * pr, is64);
        int r = readIdx(tp, 2LL * pr + 1, is64);
        float dl = g_deg[l], dr = g_deg[r];
        float wl = (dl > 0.f) ? (1.0f / dl) : 1.0f;
        float wr = (dr > 0.f) ? (1.0f / dr) : 1.0f;
        float4 a = ((const float4*)g_feat)[(size_t)l * 32 + lane];
        float4 b = ((const float4*)g_feat)[(size_t)r * 32 + lane];
        float dx = wl * a.x - wr * b.x, dy = wl * a.y - wr * b.y;
        float dz = wl * a.z - wr * b.z, dw = wl * a.w - wr * b.w;
        float s = warpSum(dx * dx + dy * dy + dz * dz + dw * dw);
        if (lane == 0) g_pos[pr] = s;
    }
}

// ---------------- launch 3: persistent f16 GEMM, 2 CTAs/SM ping-pong -----
// 296 CTAs x 128 threads (4 warps, 2m x 2n, warp tile 64x64). f16 inputs AND
// f16 accumulators: 2x HMMA rate, acc regs halved (no spills). Epilogue
// computes y = 2*dot - sqn_j in fp32, stages via stmatrix through the dead B
// buffer, streams out coalesced. Mask applied analytically in k_lse.
__global__ __launch_bounds__(128, 2) void k_mma(const void* tp) {
    extern __shared__ char dsm[];
    char* pA = dsm;                                // 32KB
    char* pB[2] = { dsm + 32768, dsm + 65536 };    // 2 x 32KB
    __shared__ float s_sqnj[2][BN];

    const int tid = threadIdx.x;
    const int lane = tid & 31, warp = tid >> 5;
    const int wm = warp >> 1, wn = warp & 1;       // 2m x 2n
    const int qrow = lane >> 2, qcol = lane & 3;
    const int is64 = g_tp64;
    const uint32_t sAaddr = smem_u32(pA);
    const uint32_t sBaddr[2] = { smem_u32(pB[0]), smem_u32(pB[1]) };
    const uint32_t sqnjaddr = smem_u32(s_sqnj);

    // ldmatrix lane address components
    const int aRow0 = wm * 64 + (lane & 15);       // + mi*16
    const int aKh   = (lane >> 4) & 1;
    const int bRowL = (lane & 7) + (((lane >> 4) & 1) << 3);   // + wn*64 + nt*16
    const int bKh   = (lane >> 3) & 1;

    // stmatrix lane address components
    const int stT = lane >> 3, stL = lane & 7;
    const int stRowBase = wm * 64 + ((stT & 1) << 3) + stL;    // + mi*16
    const int stCcBase  = wn * 8 + (stT >> 1);                 // + np*2 ; swizzle ^ stL

    const long long t0 = ((long long)blockIdx.x * TOTW) / GRID_MMA;
    const long long t1 = ((long long)(blockIdx.x + 1) * TOTW) / GRID_MMA;
    if (t0 >= t1) return;

    int cur_bm = -1;
    float psum[8], psum2[8], pmax[8];
#pragma unroll
    for (int s = 0; s < 8; s++) { psum[s] = 0.f; psum2[s] = 0.f; pmax[s] = -3.0e38f; }

    // prefetch B + sqn for first work item
    {
        int nb = (int)(t0 % NCHUNK) * BN;
#pragma unroll
        for (int q = 0; q < 16; q++) {
            int idx = tid + q * 128;               // 0..2047
            int row = idx >> 4, cc = idx & 15;
            cp_async16(sBaddr[0] + row * 256 + ((cc ^ (row & 7)) << 4),
                       g_featH + (size_t)(nb + row) * HID + cc * 8);
        }
        if (tid < 32) cp_async16(sqnjaddr + tid * 16, &g_sqn[nb + tid * 4]);
        cp_commit();
    }

    for (long long t = t0; t < t1; t++) {
        const int b = (int)((t - t0) & 1);
        const int bm = (int)(t / NCHUNK);
        const int ch = (int)(t % NCHUNK);

        if (bm != cur_bm) {
            if (cur_bm >= 0) {   // flush stats of previous bm
#pragma unroll
                for (int s = 0; s < 8; s++) {
                    float v = psum[s], v2 = psum2[s], m = pmax[s];
                    v += __shfl_xor_sync(0xffffffffu, v, 1);
                    v += __shfl_xor_sync(0xffffffffu, v, 2);
                    v2 += __shfl_xor_sync(0xffffffffu, v2, 1);
                    v2 += __shfl_xor_sync(0xffffffffu, v2, 2);
                    m = fmaxf(m, __shfl_xor_sync(0xffffffffu, m, 1));
                    m = fmaxf(m, __shfl_xor_sync(0xffffffffu, m, 2));
                    if (qcol == 0) {
                        int grow = cur_bm * 128 + wm * 64 + (s >> 1) * 16 + qrow + 8 * (s & 1);
                        atomicAdd(&g_rsum[grow], v);
                        atomicAdd(&g_rsum2[grow], v2);
                        atomicMax(&g_rmaxU[grow], encf(m));
                    }
                    psum[s] = 0.f; psum2[s] = 0.f; pmax[s] = -3.0e38f;
                }
            }
            // A tile: 128 gathered rows, fp16, swizzled; 2048 chunks of 16B
#pragma unroll
            for (int q = 0; q < 16; q++) {
                int idx = tid + q * 128;
                int row = idx >> 4, cc = idx & 15;
                int g = bm * 128 + row;
                int pair = g >> 1, side = g & 1;
                int arow = readIdx(tp, 2LL * pair + side, is64);
                cp_async16(sAaddr + row * 256 + ((cc ^ (row & 7)) << 4),
                           g_featH + (size_t)arow * HID + cc * 8);
            }
            cp_commit();
            cur_bm = bm;
        }

        // prefetch next B
        if (t + 1 < t1) {
            int nb = (int)((t + 1) % NCHUNK) * BN;
            uint32_t dst = sBaddr[b ^ 1];
#pragma unroll
            for (int q = 0; q < 16; q++) {
                int idx = tid + q * 128;
                int row = idx >> 4, cc = idx & 15;
                cp_async16(dst + row * 256 + ((cc ^ (row & 7)) << 4),
                           g_featH + (size_t)(nb + row) * HID + cc * 8);
            }
            if (tid < 32) cp_async16(sqnjaddr + (b ^ 1) * (BN * 4) + tid * 16, &g_sqn[nb + tid * 4]);
            cp_commit();
            asm volatile("cp.async.wait_group 1;" ::: "memory");
        } else {
            asm volatile("cp.async.wait_group 0;" ::: "memory");
        }
        __syncthreads();                           // (1) tile b ready

        // ---- compute 128x128 chunk: 8 kgroups x (8 LDSM.x4 + 32 HMMA f16) ----
        uint32_t acc[4][8][2];
#pragma unroll
        for (int mi = 0; mi < 4; mi++)
#pragma unroll
            for (int ni = 0; ni < 8; ni++) { acc[mi][ni][0] = 0u; acc[mi][ni][1] = 0u; }

        const uint32_t sB = sBaddr[b];
#pragma unroll
        for (int kg = 0; kg < 8; kg++) {
            uint32_t af[4][4], bf[4][4];
            const int kcA = 2 * kg + aKh;
            const int kcB = 2 * kg + bKh;
#pragma unroll
            for (int mi = 0; mi < 4; mi++) {
                int row = aRow0 + mi * 16;
                ldsm4(af[mi], sAaddr + row * 256 + ((kcA ^ (row & 7)) << 4));
            }
#pragma unroll
            for (int nt = 0; nt < 4; nt++) {
                int row = wn * 64 + nt * 16 + bRowL;
                ldsm4(bf[nt], sB + row * 256 + ((kcB ^ (row & 7)) << 4));
            }
#pragma unroll
            for (int mi = 0; mi < 4; mi++)
#pragma unroll
                for (int ni = 0; ni < 8; ni++) {
                    uint32_t bb[2] = { bf[ni >> 1][(ni & 1) * 2], bf[ni >> 1][(ni & 1) * 2 + 1] };
                    mma_f16(acc[mi][ni], af[mi], bb);
                }
        }

        __syncthreads();                           // (2) pB[b] fully consumed

        // ---- epilogue: y = 2*acc - sqn_j (fp32); stats; stmatrix into pB[b] ----
        const int jc = ch * BN;
#pragma unroll
        for (int mi = 0; mi < 4; mi++) {
            const int s0 = mi * 2, s1 = s0 + 1;
#pragma unroll
            for (int np = 0; np < 4; np++) {
                uint32_t hh[4];
#pragma unroll
                for (int d = 0; d < 2; d++) {
                    int ni = np * 2 + d;
                    int c = wn * 64 + ni * 8 + qcol * 2;
                    float sq0 = s_sqnj[b][c], sq1 = s_sqnj[b][c + 1];
                    float2 f0 = __half22float2(*(__half2*)&acc[mi][ni][0]); // (r0,c),(r0,c+1)
                    float2 f1 = __half22float2(*(__half2*)&acc[mi][ni][1]); // (r1,c),(r1,c+1)
                    float y00 = fmaf(2.f, f0.x, -sq0);
                    float y01 = fmaf(2.f, f0.y, -sq1);
                    float y10 = fmaf(2.f, f1.x, -sq0);
                    float y11 = fmaf(2.f, f1.y, -sq1);
                    __half2 a0 = __floats2half2_rn(y00, y01);
                    __half2 a1 = __floats2half2_rn(y10, y11);
                    hh[d * 2 + 0] = *(uint32_t*)&a0;
                    hh[d * 2 + 1] = *(uint32_t*)&a1;
                    if (jc + c < NODE) {
                        psum[s0] += y00 + y01;
                        psum2[s0] += y00 * y00 + y01 * y01;
                        pmax[s0] = fmaxf(pmax[s0], fmaxf(y00, y01));
                        psum[s1] += y10 + y11;
                        psum2[s1] += y10 * y10 + y11 * y11;
                        pmax[s1] = fmaxf(pmax[s1], fmaxf(y10, y11));
                    }
                }
                int rr = stRowBase + mi * 16;
                int cc = stCcBase + np * 2;
                stsm4(sB + rr * 256 + ((cc ^ stL) << 4), hh);
            }
        }

        __syncthreads();                           // (3) staging complete

        // ---- coalesced copy-out: 16 x (LDS.128 + STG.128) per thread ----
#pragma unroll
        for (int q = 0; q < 16; q++) {
            int idx = tid + q * 128;
            int row = idx >> 4, cc = idx & 15;
            uint4 v;
            uint32_t a = sB + row * 256 + ((cc ^ (row & 7)) << 4);
            asm volatile("ld.shared.v4.u32 {%0,%1,%2,%3}, [%4];"
                : "=r"(v.x), "=r"(v.y), "=r"(v.z), "=r"(v.w) : "r"(a));
            *(uint4*)(g_Y + (size_t)(cur_bm * 128 + row) * NPAD + jc + cc * 8) = v;
        }

        __syncthreads();                           // (4) copy done before prefetch reuses pB[b]
    }

    // final flush
#pragma unroll
    for (int s = 0; s < 8; s++) {
        float v = psum[s], v2 = psum2[s], m = pmax[s];
        v += __shfl_xor_sync(0xffffffffu, v, 1);
        v += __shfl_xor_sync(0xffffffffu, v, 2);
        v2 += __shfl_xor_sync(0xffffffffu, v2, 1);
        v2 += __shfl_xor_sync(0xffffffffu, v2, 2);
        m = fmaxf(m, __shfl_xor_sync(0xffffffffu, m, 1));
        m = fmaxf(m, __shfl_xor_sync(0xffffffffu, m, 2));
        if (qcol == 0) {
            int grow = cur_bm * 128 + wm * 64 + (s >> 1) * 16 + qrow + 8 * (s & 1);
            atomicAdd(&g_rsum[grow], v);
            atomicAdd(&g_rsum2[grow], v2);
            atomicMax(&g_rmaxU[grow], encf(m));
        }
    }
}

// ---------------- launch 4: logsumexp with analytic mask correction --------
__device__ float blockSum(float v) {
    __shared__ float scr[8];
    __shared__ float bc;
    v = warpSum(v);
    if ((threadIdx.x & 31) == 0) scr[threadIdx.x >> 5] = v;
    __syncthreads();
    if (threadIdx.x < 32) {
        float t = (threadIdx.x < 8) ? scr[threadIdx.x] : 0.f;
        t = warpSum(t);
        if (threadIdx.x == 0) bc = t;
    }
    __syncthreads();
    float r = bc;
    __syncthreads();
    return r;
}

__device__ __forceinline__ void unpack8(uint4 v, float* f) {
    float2 a = __half22float2(*(__half2*)&v.x);
    float2 b = __half22float2(*(__half2*)&v.y);
    float2 c = __half22float2(*(__half2*)&v.z);
    float2 d = __half22float2(*(__half2*)&v.w);
    f[0] = a.x; f[1] = a.y; f[2] = b.x; f[3] = b.y;
    f[4] = c.x; f[5] = c.y; f[6] = d.x; f[7] = d.y;
}

__global__ __launch_bounds__(256) void k_lse(const void* tp) {
    const int row = blockIdx.x;
    const int tid = threadIdx.x;
    const int pair = row >> 1, side = row & 1;
    const int is64 = g_tp64;
    const int l = readIdx(tp, 2LL * pair, is64);
    const int r = readIdx(tp, 2LL * pair + 1, is64);
    const float pos = g_pos[pair];
    const float sqa = g_sqn[side ? r : l];
    const float cm = pos - sqa + GAMMA_F;

    // analytic unmasked values at masked columns (exact identities):
    //   a==col -> y_old = sqa ;  partner col -> y_old = sqa - pos
    float yol, yor, ynl, ynr;
    float sum = g_rsum[row], sum2 = g_rsum2[row];
    if (l != r) {
        yol = side ? (sqa - pos) : sqa;
        yor = side ? sqa : (sqa - pos);
        ynl = -cm; ynr = -cm;
        sum += (ynl - yol) + (ynr - yor);
        sum2 += (ynl * ynl - yol * yol) + (ynr * ynr - yor * yor);
    } else {
        yol = sqa;
        ynl = -yol - 2.0f * cm;       // mask = -1 when l == r
        yor = 0.f; ynr = 0.f;
        sum += ynl - yol;
        sum2 += ynl * ynl - yol * yol;
    }
    const float mean = sum * (1.0f / 30000.0f);
    const float var = sum2 * (1.0f / 30000.0f) - mean * mean;
    const float a = LAMB_F / sqrtf(var);
    const float mx = decf(g_rmaxU[row]);

    const uint4* x4 = (const uint4*)(g_Y + (size_t)row * NPAD);
    float se = 0.f;
    for (int i = tid; i < 3750; i += 256) {   // 3750*8 = 30000
        float f[8];
        unpack8(x4[i], f);
#pragma unroll
        for (int c = 0; c < 8; c++) se += __expf(a * (f[c] - mx));
    }
    float setot = blockSum(se);
    if (tid == 0) {
        setot += __expf(a * (ynl - mx)) - __expf(a * (yol - mx));
        if (l != r) setot += __expf(a * (ynr - mx)) - __expf(a * (yor - mx));
        float lse = a * (mx - mean) + TAU_F + logf(setot);
        atomicAdd(&g_acc, (double)lse);
    }
}

__global__ void k_final(float* out) {
    if (threadIdx.x == 0 && blockIdx.x == 0)
        out[0] = (float)(g_acc / (double)NBATCH);
}

// ---------------- launch ----------------
extern "C" void kernel_launch(void* const* d_in, const int* in_sizes, int n_in,
                              void* d_out, int out_size) {
    const void* tp = nullptr;
    const void* adj = nullptr;
    const float* emb = nullptr;
    for (int i = 0; i < n_in; i++) {
        if (in_sizes[i] == NBATCH * 2)        tp  = d_in[i];
        else if (in_sizes[i] == 2 * NE)       adj = d_in[i];
        else if (in_sizes[i] == NODE * HID)   emb = (const float*)d_in[i];
    }
    float* out = (float*)d_out;

    k_zero<<<2048, 256>>>(tp, adj);                                        // idx 0
    k_scatter<<<(int)(((long long)NE * 32 + 255) / 256), 256>>>(adj, emb); // idx 1
    k_prep<<<NPAD / 8 + NBATCH / 8, 256>>>(tp);                            // idx 2

    // dynamic smem: A 32KB + 2 x B 32KB = 96KB per CTA (2 CTAs/SM)
    cudaFuncSetAttribute(k_mma, cudaFuncAttributeMaxDynamicSharedMemorySize, 98304);
    k_mma<<<GRID_MMA, 128, 98304>>>(tp);                                   // idx 3 (ncu)

    k_lse<<<AROWS, 256>>>(tp);                                             // idx 4
    k_final<<<1, 1>>>(out);                                                // idx 5
}